// round 9
// baseline (speedup 1.0000x reference)
#include <cuda_runtime.h>
#include <math.h>

// ---------------- problem constants ----------------
constexpr int Nn  = 50000;
constexpr int Ee  = 800000;
constexpr int ET  = Ee + Nn;          // 850000
constexpr int Hh  = 4;
constexpr int Cc  = 16;
constexpr int F   = Hh * Cc;          // 64
constexpr int IND = 128;
constexpr int NGr = 128;
constexpr float NEG   = 0.2f;
constexpr float EPSbn = 1e-5f;
constexpr int GNB  = 80;              // gemm nodes per block (50000/80=625)

// ---------------- scratch ----------------
__device__ float g_h  [Nn * F];
__device__ float g_x  [Nn * F];
__device__ float g_as [Nn * Hh];      // float4[Nn]
__device__ float g_ad [Nn * Hh];
__device__ float g_al [ET * Hh];      // e-values by CSR position, float4[ET]
__device__ int   g_deg [Nn];          // zero-initialized; re-zeroed by k_scan
__device__ int   g_row [Nn + 1];      // CSR row starts, row[Nn]=ET
__device__ int   g_cur [Nn];
__device__ int   g_csr [ET];          // edge id by CSR position
__device__ int   g_srcn[ET];          // src node by CSR position

__device__ __forceinline__ void edge_sd(int e, const int* __restrict__ ei,
                                        int& s, int& d) {
    if (e < Ee) { s = ei[e]; d = ei[Ee + e]; }
    else        { s = e - Ee; d = e - Ee; }
}

// ---------------- CSR build ----------------
__global__ void k_deg(const int* __restrict__ ei) {
    int e = blockIdx.x * blockDim.x + threadIdx.x;
    if (e >= ET) return;
    int s, d; edge_sd(e, ei, s, d);
    atomicAdd(&g_deg[d], 1);
}

// Single-block full scan: 1024 threads, 49 elems each (50176 >= 50000).
// Writes g_row (exclusive), g_cur (copy), re-zeros g_deg for the next replay.
__global__ void k_scan() {
    constexpr int PER = 49;
    __shared__ int wsum[32];
    int tid = threadIdx.x;
    int base = tid * PER;
    int s = 0;
    for (int j = 0; j < PER; j++) {
        int i = base + j;
        if (i < Nn) s += g_deg[i];
    }
    // block exclusive scan of s
    int lane = tid & 31, wid = tid >> 5;
    int v = s;
#pragma unroll
    for (int off = 1; off < 32; off <<= 1) {
        int t = __shfl_up_sync(0xffffffffu, v, off);
        if (lane >= off) v += t;
    }
    if (lane == 31) wsum[wid] = v;
    __syncthreads();
    if (wid == 0) {
        int w = wsum[lane];
#pragma unroll
        for (int off = 1; off < 32; off <<= 1) {
            int t = __shfl_up_sync(0xffffffffu, w, off);
            if (lane >= off) w += t;
        }
        wsum[lane] = w;
    }
    __syncthreads();
    int run = v - s + (wid ? wsum[wid - 1] : 0);
    for (int j = 0; j < PER; j++) {
        int i = base + j;
        if (i < Nn) {
            int d = g_deg[i];
            g_row[i] = run;
            g_cur[i] = run;
            g_deg[i] = 0;          // restore invariant for next replay
            run += d;
        }
    }
    if (tid == 1023) g_row[Nn] = ET;
}

__global__ void k_fill(const int* __restrict__ ei) {
    int e = blockIdx.x * blockDim.x + threadIdx.x;
    if (e >= ET) return;
    int s, d; edge_sd(e, ei, s, d);
    int pos = atomicAdd(&g_cur[d], 1);
    g_csr[pos]  = e;
    g_srcn[pos] = s;
}

// ---------------- GEMM + fused attention dots ----------------
// 256 threads, GNB nodes/block. Thread (oq=tid&15, ng=tid>>4) computes
// channels {oq,oq+16,oq+32,oq+48} (one per head) for nodes ng*5..ng*5+4.
// Epilogue: width-16 shuffle reduce -> per-node float4 att dots.
template <int K>
__global__ void k_gemm(const float* __restrict__ xparam,
                       const float* __restrict__ W,
                       const float* __restrict__ att_s,
                       const float* __restrict__ att_d, int use_gx) {
    extern __shared__ float smem[];
    float (*sW)[K + 1] = (float(*)[K + 1])smem;
    float (*sX)[K + 1] = (float(*)[K + 1])(smem + F * (K + 1));
    const float* __restrict__ xin = use_gx ? (const float*)g_x : xparam;
    const int tid = threadIdx.x;
    const int base = blockIdx.x * GNB;

    for (int i = tid; i < F * K / 4; i += 256) {
        float4 w = ((const float4*)W)[i];
        int f = i * 4, r = f / K, c = f % K;
        sW[r][c] = w.x; sW[r][c + 1] = w.y; sW[r][c + 2] = w.z; sW[r][c + 3] = w.w;
    }
    const float4* __restrict__ xv = (const float4*)(xin + (size_t)base * K);
    for (int i = tid; i < GNB * K / 4; i += 256) {
        float4 v = xv[i];
        int f = i * 4, r = f / K, c = f % K;
        sX[r][c] = v.x; sX[r][c + 1] = v.y; sX[r][c + 2] = v.z; sX[r][c + 3] = v.w;
    }
    __syncthreads();

    const int oq = tid & 15, ng = tid >> 4;
    float acc[4][5];
#pragma unroll
    for (int j = 0; j < 4; j++)
#pragma unroll
        for (int i = 0; i < 5; i++) acc[j][i] = 0.f;

    for (int k = 0; k < K; k++) {
        float w0 = sW[oq][k], w1 = sW[oq + 16][k];
        float w2 = sW[oq + 32][k], w3 = sW[oq + 48][k];
#pragma unroll
        for (int i = 0; i < 5; i++) {
            float xk = sX[ng * 5 + i][k];
            acc[0][i] = fmaf(w0, xk, acc[0][i]);
            acc[1][i] = fmaf(w1, xk, acc[1][i]);
            acc[2][i] = fmaf(w2, xk, acc[2][i]);
            acc[3][i] = fmaf(w3, xk, acc[3][i]);
        }
    }

    float ats[4], atd[4];
#pragma unroll
    for (int j = 0; j < 4; j++) {
        ats[j] = att_s[j * 16 + oq];
        atd[j] = att_d[j * 16 + oq];
    }
    float4* __restrict__ as4 = (float4*)g_as;
    float4* __restrict__ ad4 = (float4*)g_ad;

#pragma unroll
    for (int i = 0; i < 5; i++) {
        int n = base + ng * 5 + i;
#pragma unroll
        for (int j = 0; j < 4; j++)
            g_h[(size_t)n * F + oq + 16 * j] = acc[j][i];
        float vs0 = acc[0][i] * ats[0], vs1 = acc[1][i] * ats[1];
        float vs2 = acc[2][i] * ats[2], vs3 = acc[3][i] * ats[3];
        float vd0 = acc[0][i] * atd[0], vd1 = acc[1][i] * atd[1];
        float vd2 = acc[2][i] * atd[2], vd3 = acc[3][i] * atd[3];
#pragma unroll
        for (int off = 8; off; off >>= 1) {
            vs0 += __shfl_down_sync(0xffffffffu, vs0, off, 16);
            vs1 += __shfl_down_sync(0xffffffffu, vs1, off, 16);
            vs2 += __shfl_down_sync(0xffffffffu, vs2, off, 16);
            vs3 += __shfl_down_sync(0xffffffffu, vs3, off, 16);
            vd0 += __shfl_down_sync(0xffffffffu, vd0, off, 16);
            vd1 += __shfl_down_sync(0xffffffffu, vd1, off, 16);
            vd2 += __shfl_down_sync(0xffffffffu, vd2, off, 16);
            vd3 += __shfl_down_sync(0xffffffffu, vd3, off, 16);
        }
        if (oq == 0) {
            as4[n] = make_float4(vs0, vs1, vs2, vs3);
            ad4[n] = make_float4(vd0, vd1, vd2, vd3);
        }
    }
}

// ---------------- fused edge pipeline: logits+softmax+agg+BN ----------------
__global__ void k_layer(float4* __restrict__ alpha_out,
                        const float* __restrict__ bias, const float* __restrict__ gamma,
                        const float* __restrict__ beta, const float* __restrict__ mu,
                        const float* __restrict__ var) {
    int node = (blockIdx.x * blockDim.x + threadIdx.x) >> 5;
    int lane = threadIdx.x & 31;
    int ro = g_row[node], dg = g_row[node + 1] - ro;
    const float4* __restrict__ as4 = (const float4*)g_as;
    float4* __restrict__ al4 = (float4*)g_al;
    float4 ad = ((const float4*)g_ad)[node];

    // phase A: logits -> g_al (CSR order), per-head max
    float m0 = -1e30f, m1 = -1e30f, m2 = -1e30f, m3 = -1e30f;
    for (int i = lane; i < dg; i += 32) {
        int s = g_srcn[ro + i];
        float4 as = as4[s];
        float l0 = as.x + ad.x; l0 = l0 > 0.f ? l0 : NEG * l0;
        float l1 = as.y + ad.y; l1 = l1 > 0.f ? l1 : NEG * l1;
        float l2 = as.z + ad.z; l2 = l2 > 0.f ? l2 : NEG * l2;
        float l3 = as.w + ad.w; l3 = l3 > 0.f ? l3 : NEG * l3;
        al4[ro + i] = make_float4(l0, l1, l2, l3);
        m0 = fmaxf(m0, l0); m1 = fmaxf(m1, l1);
        m2 = fmaxf(m2, l2); m3 = fmaxf(m3, l3);
    }
#pragma unroll
    for (int off = 16; off; off >>= 1) {
        m0 = fmaxf(m0, __shfl_xor_sync(0xffffffffu, m0, off));
        m1 = fmaxf(m1, __shfl_xor_sync(0xffffffffu, m1, off));
        m2 = fmaxf(m2, __shfl_xor_sync(0xffffffffu, m2, off));
        m3 = fmaxf(m3, __shfl_xor_sync(0xffffffffu, m3, off));
    }
    __syncwarp();
    // phase A2: exp in place, per-head sum
    float z0 = 0.f, z1 = 0.f, z2 = 0.f, z3 = 0.f;
    for (int i = lane; i < dg; i += 32) {
        float4 l = al4[ro + i];
        float e0 = __expf(l.x - m0), e1 = __expf(l.y - m1);
        float e2 = __expf(l.z - m2), e3 = __expf(l.w - m3);
        al4[ro + i] = make_float4(e0, e1, e2, e3);
        z0 += e0; z1 += e1; z2 += e2; z3 += e3;
    }
#pragma unroll
    for (int off = 16; off; off >>= 1) {
        z0 += __shfl_xor_sync(0xffffffffu, z0, off);
        z1 += __shfl_xor_sync(0xffffffffu, z1, off);
        z2 += __shfl_xor_sync(0xffffffffu, z2, off);
        z3 += __shfl_xor_sync(0xffffffffu, z3, off);
    }
    float i0 = 1.f / z0, i1 = 1.f / z1, i2 = 1.f / z2, i3 = 1.f / z3;
    __syncwarp();

    if (alpha_out) {   // layer 0: normalized alphas by edge id
        for (int i = lane; i < dg; i += 32) {
            int e = g_csr[ro + i];
            float4 ev = al4[ro + i];
            alpha_out[e] = make_float4(ev.x * i0, ev.y * i1, ev.z * i2, ev.w * i3);
        }
    }

    // phase B: aggregate; lane owns channels {2*lane, 2*lane+1}, head=lane>>3
    float inv = (lane & 16) ? ((lane & 8) ? i3 : i2) : ((lane & 8) ? i1 : i0);
    float ax = 0.f, ay = 0.f;
    int c = lane * 2;
    for (int i = 0; i < dg; i++) {
        int s = g_srcn[ro + i];              // broadcast
        float4 ev = al4[ro + i];             // broadcast
        float al = (lane & 16) ? ((lane & 8) ? ev.w : ev.z)
                               : ((lane & 8) ? ev.y : ev.x);
        float2 hv = *(const float2*)(g_h + (size_t)s * F + c);
        ax = fmaf(al, hv.x, ax);
        ay = fmaf(al, hv.y, ay);
    }
    ax *= inv; ay *= inv;

    float2 bi = *(const float2*)(bias + c);
    float2 ga = *(const float2*)(gamma + c);
    float2 be = *(const float2*)(beta + c);
    float2 m_ = *(const float2*)(mu + c);
    float2 va = *(const float2*)(var + c);
    float vx = fmaxf(ax + bi.x, 0.f);
    vx = ga.x * (vx - m_.x) * rsqrtf(va.x + EPSbn) + be.x;
    float vy = fmaxf(ay + bi.y, 0.f);
    vy = ga.y * (vy - m_.y) * rsqrtf(va.y + EPSbn) + be.y;
    *(float2*)(g_x + (size_t)node * F + c) = make_float2(vx, vy);
}

// ---------------- head: pool + FC + sigmoid ----------------
__global__ void k_head(const int* __restrict__ batch,
                       const float* __restrict__ fcW, const float* __restrict__ fcb,
                       float* __restrict__ out) {
    __shared__ float sh[4][F];
    int g = blockIdx.x;
    int tid = threadIdx.x;            // 256
    int sub = tid >> 6, c = tid & 63;
    int lo = 0, hi = Nn;
    while (lo < hi) { int m = (lo + hi) >> 1; if (batch[m] < g) lo = m + 1; else hi = m; }
    int r0 = lo;
    lo = 0; hi = Nn;
    while (lo < hi) { int m = (lo + hi) >> 1; if (batch[m] < g + 1) lo = m + 1; else hi = m; }
    int r1 = lo;

    float acc = 0.f;
    for (int n = r0 + sub; n < r1; n += 4) acc += g_x[(size_t)n * F + c];
    sh[sub][c] = acc;
    __syncthreads();
    if (sub == 0) {
        float cnt = fmaxf((float)(r1 - r0), 1.f);
        float t = (sh[0][c] + sh[1][c] + sh[2][c] + sh[3][c]) / cnt * fcW[c];
        sh[0][c] = t;
    }
    __syncthreads();
    if (tid == 0) {
        float z = fcb[0];
        for (int i = 0; i < F; i++) z += sh[0][i];
        out[g] = 1.f / (1.f + expf(-z));
    }
}

// ---------------- launch ----------------
extern "C" void kernel_launch(void* const* d_in, const int* in_sizes, int n_in,
                              void* d_out, int out_size) {
    const float* x     = (const float*)d_in[0];
    const int*   ei    = (const int*)  d_in[1];
    const int*   batch = (const int*)  d_in[2];
    const float* P[3][8];
    for (int l = 0; l < 3; l++)
        for (int j = 0; j < 8; j++)
            P[l][j] = (const float*)d_in[3 + l * 8 + j];
    const float* fcW = (const float*)d_in[27];
    const float* fcb = (const float*)d_in[28];

    float* out = (float*)d_out;
    float4* alpha_out = (out_size >= NGr + ET * Hh) ? (float4*)(out + NGr) : nullptr;

    const int TB = 256;
    const int gEdge  = (ET + TB - 1) / TB;
    const int gLayer = Nn / 8;                 // warp per node
    const int gGemm  = Nn / GNB;               // 625

    const int smem0 = (F + GNB) * (IND + 1) * sizeof(float);
    const int smem1 = (F + GNB) * (F + 1) * sizeof(float);
    cudaFuncSetAttribute(k_gemm<IND>, cudaFuncAttributeMaxDynamicSharedMemorySize, smem0);
    cudaFuncSetAttribute(k_gemm<F>,   cudaFuncAttributeMaxDynamicSharedMemorySize, smem1);

    // CSR build (g_deg starts zero: zero-init at load, re-zeroed by k_scan)
    k_deg<<<gEdge, TB>>>(ei);
    k_scan<<<1, 1024>>>();
    k_fill<<<gEdge, TB>>>(ei);

    for (int l = 0; l < 3; l++) {
        if (l == 0) k_gemm<IND><<<gGemm, TB, smem0>>>(x, P[0][0], P[0][1], P[0][2], 0);
        else        k_gemm<F>  <<<gGemm, TB, smem1>>>(x, P[l][0], P[l][1], P[l][2], 1);
        k_layer<<<gLayer, TB>>>(l == 0 ? alpha_out : nullptr,
                                P[l][3], P[l][4], P[l][5], P[l][6], P[l][7]);
    }
    k_head<<<NGr, TB>>>(batch, fcW, fcb, out);
}

// round 10
// speedup vs baseline: 1.2260x; 1.2260x over previous
#include <cuda_runtime.h>
#include <math.h>

// ---------------- problem constants ----------------
constexpr int Nn  = 50000;
constexpr int Ee  = 800000;
constexpr int ET  = Ee + Nn;          // 850000
constexpr int Hh  = 4;
constexpr int Cc  = 16;
constexpr int F   = Hh * Cc;          // 64
constexpr int IND = 128;
constexpr int NGr = 128;
constexpr float NEG   = 0.2f;
constexpr float EPSbn = 1e-5f;
constexpr int GNB  = 80;              // gemm nodes per block (50000/80=625)

// ---------------- scratch ----------------
__device__ float g_h  [Nn * F];
__device__ float g_x  [Nn * F];
__device__ float g_as [Nn * Hh];      // float4[Nn]
__device__ float g_ad [Nn * Hh];
__device__ float g_al [ET * Hh];      // e-values by CSR position, float4[ET]
__device__ int   g_deg [Nn];          // zero-init; re-zeroed by k_scan each call
__device__ int   g_row [Nn + 1];      // CSR row starts, row[Nn]=ET
__device__ int   g_cur [Nn];
__device__ int   g_csr [ET];          // edge id by CSR position
__device__ int   g_srcn[ET];          // src node by CSR position

// ---------------- CSR build ----------------
__global__ void k_deg(const int* __restrict__ dst) {
    int e = blockIdx.x * blockDim.x + threadIdx.x;
    if (e >= ET) return;
    int d = (e < Ee) ? dst[e] : (e - Ee);
    atomicAdd(&g_deg[d], 1);
}

// Single-block scan over coalesced 1024-wide tiles.
// Writes g_row (exclusive), g_cur (copy), re-zeros g_deg.
__global__ void k_scan() {
    __shared__ int wsum[32];
    __shared__ int s_off;
    int tid = threadIdx.x, lane = tid & 31, wid = tid >> 5;
    if (tid == 0) s_off = 0;
    __syncthreads();
    for (int t0 = 0; t0 < Nn; t0 += 1024) {
        int i = t0 + tid;
        int d = (i < Nn) ? g_deg[i] : 0;
        int v = d;
#pragma unroll
        for (int off = 1; off < 32; off <<= 1) {
            int t = __shfl_up_sync(0xffffffffu, v, off);
            if (lane >= off) v += t;
        }
        if (lane == 31) wsum[wid] = v;
        __syncthreads();
        if (wid == 0) {
            int w = wsum[lane];
#pragma unroll
            for (int off = 1; off < 32; off <<= 1) {
                int t = __shfl_up_sync(0xffffffffu, w, off);
                if (lane >= off) w += t;
            }
            wsum[lane] = w;
        }
        __syncthreads();
        int excl = v - d + (wid ? wsum[wid - 1] : 0) + s_off;
        if (i < Nn) {
            g_row[i] = excl;
            g_cur[i] = excl;
            g_deg[i] = 0;          // restore invariant for next graph replay
        }
        __syncthreads();
        if (tid == 0) s_off += wsum[31];
        __syncthreads();
    }
    if (tid == 0) g_row[Nn] = ET;
}

__global__ void k_fill(const int* __restrict__ ei) {
    int e = blockIdx.x * blockDim.x + threadIdx.x;
    if (e >= ET) return;
    int s, d;
    if (e < Ee) { s = ei[e]; d = ei[Ee + e]; }
    else        { s = e - Ee; d = e - Ee; }
    int pos = atomicAdd(&g_cur[d], 1);
    g_csr[pos]  = e;
    g_srcn[pos] = s;
}

// ---------------- GEMM + fused attention dots ----------------
// 256 threads, GNB nodes/block. Thread (oq=tid&15, ng=tid>>4) computes
// channels {oq,oq+16,oq+32,oq+48} (one per head) for nodes ng*5..ng*5+4.
template <int K>
__global__ void k_gemm(const float* __restrict__ xparam,
                       const float* __restrict__ W,
                       const float* __restrict__ att_s,
                       const float* __restrict__ att_d, int use_gx) {
    extern __shared__ float smem[];
    float (*sW)[K + 1] = (float(*)[K + 1])smem;
    float (*sX)[K + 1] = (float(*)[K + 1])(smem + F * (K + 1));
    const float* __restrict__ xin = use_gx ? (const float*)g_x : xparam;
    const int tid = threadIdx.x;
    const int base = blockIdx.x * GNB;

    for (int i = tid; i < F * K / 4; i += 256) {
        float4 w = ((const float4*)W)[i];
        int f = i * 4, r = f / K, c = f % K;
        sW[r][c] = w.x; sW[r][c + 1] = w.y; sW[r][c + 2] = w.z; sW[r][c + 3] = w.w;
    }
    const float4* __restrict__ xv = (const float4*)(xin + (size_t)base * K);
    for (int i = tid; i < GNB * K / 4; i += 256) {
        float4 v = xv[i];
        int f = i * 4, r = f / K, c = f % K;
        sX[r][c] = v.x; sX[r][c + 1] = v.y; sX[r][c + 2] = v.z; sX[r][c + 3] = v.w;
    }
    __syncthreads();

    const int oq = tid & 15, ng = tid >> 4;
    float acc[4][5];
#pragma unroll
    for (int j = 0; j < 4; j++)
#pragma unroll
        for (int i = 0; i < 5; i++) acc[j][i] = 0.f;

    for (int k = 0; k < K; k++) {
        float w0 = sW[oq][k], w1 = sW[oq + 16][k];
        float w2 = sW[oq + 32][k], w3 = sW[oq + 48][k];
#pragma unroll
        for (int i = 0; i < 5; i++) {
            float xk = sX[ng * 5 + i][k];
            acc[0][i] = fmaf(w0, xk, acc[0][i]);
            acc[1][i] = fmaf(w1, xk, acc[1][i]);
            acc[2][i] = fmaf(w2, xk, acc[2][i]);
            acc[3][i] = fmaf(w3, xk, acc[3][i]);
        }
    }

    float ats[4], atd[4];
#pragma unroll
    for (int j = 0; j < 4; j++) {
        ats[j] = att_s[j * 16 + oq];
        atd[j] = att_d[j * 16 + oq];
    }
    float4* __restrict__ as4 = (float4*)g_as;
    float4* __restrict__ ad4 = (float4*)g_ad;

#pragma unroll
    for (int i = 0; i < 5; i++) {
        int n = base + ng * 5 + i;
#pragma unroll
        for (int j = 0; j < 4; j++)
            g_h[(size_t)n * F + oq + 16 * j] = acc[j][i];
        float vs0 = acc[0][i] * ats[0], vs1 = acc[1][i] * ats[1];
        float vs2 = acc[2][i] * ats[2], vs3 = acc[3][i] * ats[3];
        float vd0 = acc[0][i] * atd[0], vd1 = acc[1][i] * atd[1];
        float vd2 = acc[2][i] * atd[2], vd3 = acc[3][i] * atd[3];
#pragma unroll
        for (int off = 8; off; off >>= 1) {
            vs0 += __shfl_down_sync(0xffffffffu, vs0, off, 16);
            vs1 += __shfl_down_sync(0xffffffffu, vs1, off, 16);
            vs2 += __shfl_down_sync(0xffffffffu, vs2, off, 16);
            vs3 += __shfl_down_sync(0xffffffffu, vs3, off, 16);
            vd0 += __shfl_down_sync(0xffffffffu, vd0, off, 16);
            vd1 += __shfl_down_sync(0xffffffffu, vd1, off, 16);
            vd2 += __shfl_down_sync(0xffffffffu, vd2, off, 16);
            vd3 += __shfl_down_sync(0xffffffffu, vd3, off, 16);
        }
        if (oq == 0) {
            as4[n] = make_float4(vs0, vs1, vs2, vs3);
            ad4[n] = make_float4(vd0, vd1, vd2, vd3);
        }
    }
}

// ---------------- fused edge pipeline ----------------
// Single pass A: e = exp(leaky(logit)) directly (no max subtraction --
// logits are bounded well below exp overflow; e/z is mathematically
// identical to the max-shifted softmax).
__global__ void k_layer(float4* __restrict__ alpha_out,
                        const float* __restrict__ bias, const float* __restrict__ gamma,
                        const float* __restrict__ beta, const float* __restrict__ mu,
                        const float* __restrict__ var) {
    int node = (blockIdx.x * blockDim.x + threadIdx.x) >> 5;
    int lane = threadIdx.x & 31;
    int ro = g_row[node], dg = g_row[node + 1] - ro;
    const float4* __restrict__ as4 = (const float4*)g_as;
    float4* __restrict__ al4 = (float4*)g_al;
    float4 ad = ((const float4*)g_ad)[node];

    // phase A: e-values + z in ONE pass
    float z0 = 0.f, z1 = 0.f, z2 = 0.f, z3 = 0.f;
    for (int i = lane; i < dg; i += 32) {
        int s = g_srcn[ro + i];
        float4 as = as4[s];
        float l0 = as.x + ad.x; l0 = l0 > 0.f ? l0 : NEG * l0;
        float l1 = as.y + ad.y; l1 = l1 > 0.f ? l1 : NEG * l1;
        float l2 = as.z + ad.z; l2 = l2 > 0.f ? l2 : NEG * l2;
        float l3 = as.w + ad.w; l3 = l3 > 0.f ? l3 : NEG * l3;
        float e0 = __expf(l0), e1 = __expf(l1);
        float e2 = __expf(l2), e3 = __expf(l3);
        al4[ro + i] = make_float4(e0, e1, e2, e3);
        z0 += e0; z1 += e1; z2 += e2; z3 += e3;
    }
#pragma unroll
    for (int off = 16; off; off >>= 1) {
        z0 += __shfl_xor_sync(0xffffffffu, z0, off);
        z1 += __shfl_xor_sync(0xffffffffu, z1, off);
        z2 += __shfl_xor_sync(0xffffffffu, z2, off);
        z3 += __shfl_xor_sync(0xffffffffu, z3, off);
    }
    float i0 = 1.f / z0, i1 = 1.f / z1, i2 = 1.f / z2, i3 = 1.f / z3;
    __syncwarp();

    if (alpha_out) {   // layer 0: normalized alphas by edge id
        for (int i = lane; i < dg; i += 32) {
            int e = g_csr[ro + i];
            float4 ev = al4[ro + i];
            alpha_out[e] = make_float4(ev.x * i0, ev.y * i1, ev.z * i2, ev.w * i3);
        }
    }

    // phase B: aggregate; lane owns channels {2*lane, 2*lane+1}
    float inv = (lane & 16) ? ((lane & 8) ? i3 : i2) : ((lane & 8) ? i1 : i0);
    float ax = 0.f, ay = 0.f;
    int c = lane * 2;
    for (int i = 0; i < dg; i++) {
        int s = g_srcn[ro + i];              // broadcast
        float4 ev = al4[ro + i];             // broadcast
        float al = (lane & 16) ? ((lane & 8) ? ev.w : ev.z)
                               : ((lane & 8) ? ev.y : ev.x);
        float2 hv = *(const float2*)(g_h + (size_t)s * F + c);
        ax = fmaf(al, hv.x, ax);
        ay = fmaf(al, hv.y, ay);
    }
    ax *= inv; ay *= inv;

    float2 bi = *(const float2*)(bias + c);
    float2 ga = *(const float2*)(gamma + c);
    float2 be = *(const float2*)(beta + c);
    float2 m_ = *(const float2*)(mu + c);
    float2 va = *(const float2*)(var + c);
    float vx = fmaxf(ax + bi.x, 0.f);
    vx = ga.x * (vx - m_.x) * rsqrtf(va.x + EPSbn) + be.x;
    float vy = fmaxf(ay + bi.y, 0.f);
    vy = ga.y * (vy - m_.y) * rsqrtf(va.y + EPSbn) + be.y;
    *(float2*)(g_x + (size_t)node * F + c) = make_float2(vx, vy);
}

// ---------------- head: pool + FC + sigmoid ----------------
__global__ void k_head(const int* __restrict__ batch,
                       const float* __restrict__ fcW, const float* __restrict__ fcb,
                       float* __restrict__ out) {
    __shared__ float sh[4][F];
    int g = blockIdx.x;
    int tid = threadIdx.x;            // 256
    int sub = tid >> 6, c = tid & 63;
    int lo = 0, hi = Nn;
    while (lo < hi) { int m = (lo + hi) >> 1; if (batch[m] < g) lo = m + 1; else hi = m; }
    int r0 = lo;
    lo = 0; hi = Nn;
    while (lo < hi) { int m = (lo + hi) >> 1; if (batch[m] < g + 1) lo = m + 1; else hi = m; }
    int r1 = lo;

    float acc = 0.f;
    for (int n = r0 + sub; n < r1; n += 4) acc += g_x[(size_t)n * F + c];
    sh[sub][c] = acc;
    __syncthreads();
    if (sub == 0) {
        float cnt = fmaxf((float)(r1 - r0), 1.f);
        sh[0][c] = (sh[0][c] + sh[1][c] + sh[2][c] + sh[3][c]) / cnt * fcW[c];
    }
    __syncthreads();
    if (tid == 0) {
        float z = fcb[0];
        for (int i = 0; i < F; i++) z += sh[0][i];
        out[g] = 1.f / (1.f + expf(-z));
    }
}

// ---------------- launch ----------------
extern "C" void kernel_launch(void* const* d_in, const int* in_sizes, int n_in,
                              void* d_out, int out_size) {
    const float* x     = (const float*)d_in[0];
    const int*   ei    = (const int*)  d_in[1];
    const int*   batch = (const int*)  d_in[2];
    const float* P[3][8];
    for (int l = 0; l < 3; l++)
        for (int j = 0; j < 8; j++)
            P[l][j] = (const float*)d_in[3 + l * 8 + j];
    const float* fcW = (const float*)d_in[27];
    const float* fcb = (const float*)d_in[28];

    float* out = (float*)d_out;
    float4* alpha_out = (out_size >= NGr + ET * Hh) ? (float4*)(out + NGr) : nullptr;

    const int TB = 256;
    const int gEdge  = (ET + TB - 1) / TB;
    const int gLayer = Nn / 8;                 // warp per node
    const int gGemm  = Nn / GNB;               // 625

    const int smem0 = (F + GNB) * (IND + 1) * sizeof(float);
    const int smem1 = (F + GNB) * (F + 1) * sizeof(float);
    cudaFuncSetAttribute(k_gemm<IND>, cudaFuncAttributeMaxDynamicSharedMemorySize, smem0);
    cudaFuncSetAttribute(k_gemm<F>,   cudaFuncAttributeMaxDynamicSharedMemorySize, smem1);

    // CSR build
    k_deg<<<gEdge, TB>>>(ei + Ee);       // dst half only
    k_scan<<<1, 1024>>>();
    k_fill<<<gEdge, TB>>>(ei);

    for (int l = 0; l < 3; l++) {
        if (l == 0) k_gemm<IND><<<gGemm, TB, smem0>>>(x, P[0][0], P[0][1], P[0][2], 0);
        else        k_gemm<F>  <<<gGemm, TB, smem1>>>(x, P[l][0], P[l][1], P[l][2], 1);
        k_layer<<<gLayer, TB>>>(l == 0 ? alpha_out : nullptr,
                                P[l][3], P[l][4], P[l][5], P[l][6], P[l][7]);
    }
    k_head<<<NGr, TB>>>(batch, fcW, fcb, out);
}

// round 11
// speedup vs baseline: 1.3670x; 1.1150x over previous
#include <cuda_runtime.h>
#include <math.h>

// ---------------- problem constants ----------------
constexpr int Nn  = 50000;
constexpr int Ee  = 800000;
constexpr int ET  = Ee + Nn;          // 850000
constexpr int Hh  = 4;
constexpr int Cc  = 16;
constexpr int F   = Hh * Cc;          // 64
constexpr int IND = 128;
constexpr int NGr = 128;
constexpr float NEG   = 0.2f;
constexpr float EPSbn = 1e-5f;
constexpr int GNB  = 80;              // gemm nodes per block (50000/80=625)

// ---------------- scratch ----------------
__device__ float g_h  [Nn * F];
__device__ float g_x  [Nn * F];
__device__ float g_as [Nn * Hh];      // float4[Nn]
__device__ float g_ad [Nn * Hh];
__device__ float g_al [ET * Hh];      // e-values by CSR position, float4[ET]
__device__ int   g_deg [Nn];          // zero-init; re-zeroed by k_scan each call
__device__ int   g_row [Nn + 1];      // CSR row starts, row[Nn]=ET
__device__ int   g_cur [Nn];
__device__ int   g_csr [ET];          // edge id by CSR position
__device__ int   g_srcn[ET];          // src node by CSR position

// ---------------- CSR build ----------------
__global__ void k_deg(const int* __restrict__ dst) {
    int e = blockIdx.x * blockDim.x + threadIdx.x;
    if (e >= ET) return;
    int d = (e < Ee) ? dst[e] : (e - Ee);
    atomicAdd(&g_deg[d], 1);
}

// Single-block scan, int4 per thread (4096-wide tiles, 13 barrier rounds).
// Writes g_row (exclusive), g_cur (copy), re-zeros g_deg. Nn % 4 == 0.
__global__ void k_scan() {
    __shared__ int wsum[32];
    __shared__ int s_off;
    int tid = threadIdx.x, lane = tid & 31, wid = tid >> 5;
    if (tid == 0) s_off = 0;
    __syncthreads();
    for (int t0 = 0; t0 < Nn; t0 += 4096) {
        int i4 = t0 + tid * 4;
        int4 d = make_int4(0, 0, 0, 0);
        if (i4 < Nn) d = *(const int4*)(g_deg + i4);
        int s = d.x + d.y + d.z + d.w;
        int v = s;
#pragma unroll
        for (int off = 1; off < 32; off <<= 1) {
            int t = __shfl_up_sync(0xffffffffu, v, off);
            if (lane >= off) v += t;
        }
        if (lane == 31) wsum[wid] = v;
        __syncthreads();
        if (wid == 0) {
            int w = wsum[lane];
#pragma unroll
            for (int off = 1; off < 32; off <<= 1) {
                int t = __shfl_up_sync(0xffffffffu, w, off);
                if (lane >= off) w += t;
            }
            wsum[lane] = w;
        }
        __syncthreads();
        int excl = v - s + (wid ? wsum[wid - 1] : 0) + s_off;
        if (i4 < Nn) {
            int4 r = make_int4(excl, excl + d.x, excl + d.x + d.y,
                               excl + d.x + d.y + d.z);
            *(int4*)(g_row + i4) = r;
            *(int4*)(g_cur + i4) = r;
            *(int4*)(g_deg + i4) = make_int4(0, 0, 0, 0);
        }
        __syncthreads();
        if (tid == 0) s_off += wsum[31];
        __syncthreads();
    }
    if (tid == 0) g_row[Nn] = ET;
}

__global__ void k_fill(const int* __restrict__ ei) {
    int e = blockIdx.x * blockDim.x + threadIdx.x;
    if (e >= ET) return;
    int s, d;
    if (e < Ee) { s = ei[e]; d = ei[Ee + e]; }
    else        { s = e - Ee; d = e - Ee; }
    int pos = atomicAdd(&g_cur[d], 1);
    g_csr[pos]  = e;
    g_srcn[pos] = s;
}

// ---------------- GEMM + fused attention dots ----------------
// float4 smem staging + LDS.128, k unrolled x4: 9 LDS.128 per 80 FMA.
// Thread (oq=tid&15, ng=tid>>4): channels {oq,oq+16,oq+32,oq+48},
// nodes ng*5..ng*5+4.
template <int K>
__global__ void __launch_bounds__(256) k_gemm(
        const float* __restrict__ xparam, const float* __restrict__ W,
        const float* __restrict__ att_s, const float* __restrict__ att_d,
        int use_gx) {
    constexpr int KQ  = K / 4;
    constexpr int ST  = KQ + 1;           // float4 row stride (pad)
    extern __shared__ float4 sm4[];
    float4* sW = sm4;                     // F  x ST
    float4* sX = sm4 + F * ST;            // GNB x ST
    const float* __restrict__ xin = use_gx ? (const float*)g_x : xparam;
    const int tid = threadIdx.x;
    const int base = blockIdx.x * GNB;

    for (int i = tid; i < F * KQ; i += 256)
        sW[(i / KQ) * ST + (i % KQ)] = ((const float4*)W)[i];
    const float4* __restrict__ xv = (const float4*)(xin + (size_t)base * K);
    for (int i = tid; i < GNB * KQ; i += 256)
        sX[(i / KQ) * ST + (i % KQ)] = xv[i];
    __syncthreads();

    const int oq = tid & 15, ng = tid >> 4;
    float acc[4][5];
#pragma unroll
    for (int j = 0; j < 4; j++)
#pragma unroll
        for (int i = 0; i < 5; i++) acc[j][i] = 0.f;

    const float4* wr0 = sW + oq * ST;
    const float4* wr1 = sW + (oq + 16) * ST;
    const float4* wr2 = sW + (oq + 32) * ST;
    const float4* wr3 = sW + (oq + 48) * ST;
    const float4* xr  = sX + (ng * 5) * ST;

    for (int kq = 0; kq < KQ; kq++) {
        float4 w0 = wr0[kq], w1 = wr1[kq], w2 = wr2[kq], w3 = wr3[kq];
#pragma unroll
        for (int i = 0; i < 5; i++) {
            float4 xk = xr[i * ST + kq];
            acc[0][i] = fmaf(w0.x, xk.x, acc[0][i]);
            acc[0][i] = fmaf(w0.y, xk.y, acc[0][i]);
            acc[0][i] = fmaf(w0.z, xk.z, acc[0][i]);
            acc[0][i] = fmaf(w0.w, xk.w, acc[0][i]);
            acc[1][i] = fmaf(w1.x, xk.x, acc[1][i]);
            acc[1][i] = fmaf(w1.y, xk.y, acc[1][i]);
            acc[1][i] = fmaf(w1.z, xk.z, acc[1][i]);
            acc[1][i] = fmaf(w1.w, xk.w, acc[1][i]);
            acc[2][i] = fmaf(w2.x, xk.x, acc[2][i]);
            acc[2][i] = fmaf(w2.y, xk.y, acc[2][i]);
            acc[2][i] = fmaf(w2.z, xk.z, acc[2][i]);
            acc[2][i] = fmaf(w2.w, xk.w, acc[2][i]);
            acc[3][i] = fmaf(w3.x, xk.x, acc[3][i]);
            acc[3][i] = fmaf(w3.y, xk.y, acc[3][i]);
            acc[3][i] = fmaf(w3.z, xk.z, acc[3][i]);
            acc[3][i] = fmaf(w3.w, xk.w, acc[3][i]);
        }
    }

    float ats[4], atd[4];
#pragma unroll
    for (int j = 0; j < 4; j++) {
        ats[j] = att_s[j * 16 + oq];
        atd[j] = att_d[j * 16 + oq];
    }
    float4* __restrict__ as4 = (float4*)g_as;
    float4* __restrict__ ad4 = (float4*)g_ad;

#pragma unroll
    for (int i = 0; i < 5; i++) {
        int n = base + ng * 5 + i;
#pragma unroll
        for (int j = 0; j < 4; j++)
            g_h[(size_t)n * F + oq + 16 * j] = acc[j][i];
        float vs0 = acc[0][i] * ats[0], vs1 = acc[1][i] * ats[1];
        float vs2 = acc[2][i] * ats[2], vs3 = acc[3][i] * ats[3];
        float vd0 = acc[0][i] * atd[0], vd1 = acc[1][i] * atd[1];
        float vd2 = acc[2][i] * atd[2], vd3 = acc[3][i] * atd[3];
#pragma unroll
        for (int off = 8; off; off >>= 1) {
            vs0 += __shfl_down_sync(0xffffffffu, vs0, off, 16);
            vs1 += __shfl_down_sync(0xffffffffu, vs1, off, 16);
            vs2 += __shfl_down_sync(0xffffffffu, vs2, off, 16);
            vs3 += __shfl_down_sync(0xffffffffu, vs3, off, 16);
            vd0 += __shfl_down_sync(0xffffffffu, vd0, off, 16);
            vd1 += __shfl_down_sync(0xffffffffu, vd1, off, 16);
            vd2 += __shfl_down_sync(0xffffffffu, vd2, off, 16);
            vd3 += __shfl_down_sync(0xffffffffu, vd3, off, 16);
        }
        if (oq == 0) {
            as4[n] = make_float4(vs0, vs1, vs2, vs3);
            ad4[n] = make_float4(vd0, vd1, vd2, vd3);
        }
    }
}

// ---------------- fused edge pipeline (one-pass softmax) ----------------
__global__ void k_layer(float4* __restrict__ alpha_out,
                        const float* __restrict__ bias, const float* __restrict__ gamma,
                        const float* __restrict__ beta, const float* __restrict__ mu,
                        const float* __restrict__ var) {
    int node = (blockIdx.x * blockDim.x + threadIdx.x) >> 5;
    int lane = threadIdx.x & 31;
    int ro = g_row[node], dg = g_row[node + 1] - ro;
    const float4* __restrict__ as4 = (const float4*)g_as;
    float4* __restrict__ al4 = (float4*)g_al;
    float4 ad = ((const float4*)g_ad)[node];

    float z0 = 0.f, z1 = 0.f, z2 = 0.f, z3 = 0.f;
    for (int i = lane; i < dg; i += 32) {
        int s = g_srcn[ro + i];
        float4 as = as4[s];
        float l0 = as.x + ad.x; l0 = l0 > 0.f ? l0 : NEG * l0;
        float l1 = as.y + ad.y; l1 = l1 > 0.f ? l1 : NEG * l1;
        float l2 = as.z + ad.z; l2 = l2 > 0.f ? l2 : NEG * l2;
        float l3 = as.w + ad.w; l3 = l3 > 0.f ? l3 : NEG * l3;
        float e0 = __expf(l0), e1 = __expf(l1);
        float e2 = __expf(l2), e3 = __expf(l3);
        al4[ro + i] = make_float4(e0, e1, e2, e3);
        z0 += e0; z1 += e1; z2 += e2; z3 += e3;
    }
#pragma unroll
    for (int off = 16; off; off >>= 1) {
        z0 += __shfl_xor_sync(0xffffffffu, z0, off);
        z1 += __shfl_xor_sync(0xffffffffu, z1, off);
        z2 += __shfl_xor_sync(0xffffffffu, z2, off);
        z3 += __shfl_xor_sync(0xffffffffu, z3, off);
    }
    float i0 = 1.f / z0, i1 = 1.f / z1, i2 = 1.f / z2, i3 = 1.f / z3;
    __syncwarp();

    if (alpha_out) {
        for (int i = lane; i < dg; i += 32) {
            int e = g_csr[ro + i];
            float4 ev = al4[ro + i];
            alpha_out[e] = make_float4(ev.x * i0, ev.y * i1, ev.z * i2, ev.w * i3);
        }
    }

    float inv = (lane & 16) ? ((lane & 8) ? i3 : i2) : ((lane & 8) ? i1 : i0);
    float ax = 0.f, ay = 0.f;
    int c = lane * 2;
    for (int i = 0; i < dg; i++) {
        int s = g_srcn[ro + i];              // broadcast
        float4 ev = al4[ro + i];             // broadcast
        float al = (lane & 16) ? ((lane & 8) ? ev.w : ev.z)
                               : ((lane & 8) ? ev.y : ev.x);
        float2 hv = *(const float2*)(g_h + (size_t)s * F + c);
        ax = fmaf(al, hv.x, ax);
        ay = fmaf(al, hv.y, ay);
    }
    ax *= inv; ay *= inv;

    float2 bi = *(const float2*)(bias + c);
    float2 ga = *(const float2*)(gamma + c);
    float2 be = *(const float2*)(beta + c);
    float2 m_ = *(const float2*)(mu + c);
    float2 va = *(const float2*)(var + c);
    float vx = fmaxf(ax + bi.x, 0.f);
    vx = ga.x * (vx - m_.x) * rsqrtf(va.x + EPSbn) + be.x;
    float vy = fmaxf(ay + bi.y, 0.f);
    vy = ga.y * (vy - m_.y) * rsqrtf(va.y + EPSbn) + be.y;
    *(float2*)(g_x + (size_t)node * F + c) = make_float2(vx, vy);
}

// ---------------- head: pool + FC + sigmoid ----------------
__global__ void k_head(const int* __restrict__ batch,
                       const float* __restrict__ fcW, const float* __restrict__ fcb,
                       float* __restrict__ out) {
    __shared__ float sh[4][F];
    int g = blockIdx.x;
    int tid = threadIdx.x;            // 256
    int sub = tid >> 6, c = tid & 63;
    int lo = 0, hi = Nn;
    while (lo < hi) { int m = (lo + hi) >> 1; if (batch[m] < g) lo = m + 1; else hi = m; }
    int r0 = lo;
    lo = 0; hi = Nn;
    while (lo < hi) { int m = (lo + hi) >> 1; if (batch[m] < g + 1) lo = m + 1; else hi = m; }
    int r1 = lo;

    float acc = 0.f;
    for (int n = r0 + sub; n < r1; n += 4) acc += g_x[(size_t)n * F + c];
    sh[sub][c] = acc;
    __syncthreads();
    if (sub == 0) {
        float cnt = fmaxf((float)(r1 - r0), 1.f);
        sh[0][c] = (sh[0][c] + sh[1][c] + sh[2][c] + sh[3][c]) / cnt * fcW[c];
    }
    __syncthreads();
    if (tid == 0) {
        float z = fcb[0];
        for (int i = 0; i < F; i++) z += sh[0][i];
        out[g] = 1.f / (1.f + expf(-z));
    }
}

// ---------------- launch ----------------
extern "C" void kernel_launch(void* const* d_in, const int* in_sizes, int n_in,
                              void* d_out, int out_size) {
    const float* x     = (const float*)d_in[0];
    const int*   ei    = (const int*)  d_in[1];
    const int*   batch = (const int*)  d_in[2];
    const float* P[3][8];
    for (int l = 0; l < 3; l++)
        for (int j = 0; j < 8; j++)
            P[l][j] = (const float*)d_in[3 + l * 8 + j];
    const float* fcW = (const float*)d_in[27];
    const float* fcb = (const float*)d_in[28];

    float* out = (float*)d_out;
    float4* alpha_out = (out_size >= NGr + ET * Hh) ? (float4*)(out + NGr) : nullptr;

    const int TB = 256;
    const int gEdge  = (ET + TB - 1) / TB;
    const int gLayer = Nn / 8;                 // warp per node
    const int gGemm  = Nn / GNB;               // 625

    const int smem0 = (F + GNB) * (IND / 4 + 1) * (int)sizeof(float4);
    const int smem1 = (F + GNB) * (F / 4 + 1) * (int)sizeof(float4);
    cudaFuncSetAttribute(k_gemm<IND>, cudaFuncAttributeMaxDynamicSharedMemorySize, smem0);
    cudaFuncSetAttribute(k_gemm<F>,   cudaFuncAttributeMaxDynamicSharedMemorySize, smem1);

    // CSR build
    k_deg<<<gEdge, TB>>>(ei + Ee);       // dst half only
    k_scan<<<1, 1024>>>();
    k_fill<<<gEdge, TB>>>(ei);

    for (int l = 0; l < 3; l++) {
        if (l == 0) k_gemm<IND><<<gGemm, TB, smem0>>>(x, P[0][0], P[0][1], P[0][2], 0);
        else        k_gemm<F>  <<<gGemm, TB, smem1>>>(x, P[l][0], P[l][1], P[l][2], 1);
        k_layer<<<gLayer, TB>>>(l == 0 ? alpha_out : nullptr,
                                P[l][3], P[l][4], P[l][5], P[l][6], P[l][7]);
    }
    k_head<<<NGr, TB>>>(batch, fcW, fcb, out);
}

// round 12
// speedup vs baseline: 1.4180x; 1.0373x over previous
#include <cuda_runtime.h>
#include <cuda_bf16.h>
#include <math.h>

// ---------------- problem constants ----------------
constexpr int Nn  = 50000;
constexpr int Ee  = 800000;
constexpr int ET  = Ee + Nn;          // 850000
constexpr int Hh  = 4;
constexpr int Cc  = 16;
constexpr int F   = Hh * Cc;          // 64
constexpr int IND = 128;
constexpr int NGr = 128;
constexpr float NEG   = 0.2f;
constexpr float EPSbn = 1e-5f;
constexpr int GNB  = 80;              // gemm nodes per block (50000/80=625)

// ---------------- scratch ----------------
__device__ __nv_bfloat16 g_hb[Nn * F];  // projected features, bf16 (gather side)
__device__ float g_x  [Nn * F];
__device__ float g_as [Nn * Hh];      // float4[Nn]
__device__ float g_ad [Nn * Hh];
__device__ float g_al [ET * Hh];      // e-values by CSR position, float4[ET]
__device__ int   g_deg [Nn];          // zero-init; re-zeroed by k_scan each call
__device__ int   g_row [Nn + 1];      // CSR row starts, row[Nn]=ET
__device__ int   g_cur [Nn];
__device__ int   g_csr [ET];          // edge id by CSR position
__device__ int   g_srcn[ET];          // src node by CSR position

// ---------------- CSR build ----------------
__global__ void k_deg(const int* __restrict__ dst) {
    int e = blockIdx.x * blockDim.x + threadIdx.x;
    if (e >= ET) return;
    int d = (e < Ee) ? dst[e] : (e - Ee);
    atomicAdd(&g_deg[d], 1);
}

// Single-block scan, int4 per thread (4096-wide tiles).
// Writes g_row (exclusive), g_cur (copy), re-zeros g_deg. Nn % 4 == 0.
__global__ void k_scan() {
    __shared__ int wsum[32];
    __shared__ int s_off;
    int tid = threadIdx.x, lane = tid & 31, wid = tid >> 5;
    if (tid == 0) s_off = 0;
    __syncthreads();
    for (int t0 = 0; t0 < Nn; t0 += 4096) {
        int i4 = t0 + tid * 4;
        int4 d = make_int4(0, 0, 0, 0);
        if (i4 < Nn) d = *(const int4*)(g_deg + i4);
        int s = d.x + d.y + d.z + d.w;
        int v = s;
#pragma unroll
        for (int off = 1; off < 32; off <<= 1) {
            int t = __shfl_up_sync(0xffffffffu, v, off);
            if (lane >= off) v += t;
        }
        if (lane == 31) wsum[wid] = v;
        __syncthreads();
        if (wid == 0) {
            int w = wsum[lane];
#pragma unroll
            for (int off = 1; off < 32; off <<= 1) {
                int t = __shfl_up_sync(0xffffffffu, w, off);
                if (lane >= off) w += t;
            }
            wsum[lane] = w;
        }
        __syncthreads();
        int excl = v - s + (wid ? wsum[wid - 1] : 0) + s_off;
        if (i4 < Nn) {
            int4 r = make_int4(excl, excl + d.x, excl + d.x + d.y,
                               excl + d.x + d.y + d.z);
            *(int4*)(g_row + i4) = r;
            *(int4*)(g_cur + i4) = r;
            *(int4*)(g_deg + i4) = make_int4(0, 0, 0, 0);
        }
        __syncthreads();
        if (tid == 0) s_off += wsum[31];
        __syncthreads();
    }
    if (tid == 0) g_row[Nn] = ET;
}

__global__ void k_fill(const int* __restrict__ ei) {
    int e = blockIdx.x * blockDim.x + threadIdx.x;
    if (e >= ET) return;
    int s, d;
    if (e < Ee) { s = ei[e]; d = ei[Ee + e]; }
    else        { s = e - Ee; d = e - Ee; }
    int pos = atomicAdd(&g_cur[d], 1);
    g_csr[pos]  = e;
    g_srcn[pos] = s;
}

// ---------------- GEMM + fused attention dots ----------------
// float4 smem staging + LDS.128. Thread (oq=tid&15, ng=tid>>4): channels
// {oq,oq+16,oq+32,oq+48}, nodes ng*5..ng*5+4. h stored bf16 (gather side);
// attention dots computed and stored fp32.
template <int K>
__global__ void __launch_bounds__(256) k_gemm(
        const float* __restrict__ xparam, const float* __restrict__ W,
        const float* __restrict__ att_s, const float* __restrict__ att_d,
        int use_gx) {
    constexpr int KQ  = K / 4;
    constexpr int ST  = KQ + 1;           // float4 row stride (pad)
    extern __shared__ float4 sm4[];
    float4* sW = sm4;                     // F  x ST
    float4* sX = sm4 + F * ST;            // GNB x ST
    const float* __restrict__ xin = use_gx ? (const float*)g_x : xparam;
    const int tid = threadIdx.x;
    const int base = blockIdx.x * GNB;

    for (int i = tid; i < F * KQ; i += 256)
        sW[(i / KQ) * ST + (i % KQ)] = ((const float4*)W)[i];
    const float4* __restrict__ xv = (const float4*)(xin + (size_t)base * K);
    for (int i = tid; i < GNB * KQ; i += 256)
        sX[(i / KQ) * ST + (i % KQ)] = xv[i];
    __syncthreads();

    const int oq = tid & 15, ng = tid >> 4;
    float acc[4][5];
#pragma unroll
    for (int j = 0; j < 4; j++)
#pragma unroll
        for (int i = 0; i < 5; i++) acc[j][i] = 0.f;

    const float4* wr0 = sW + oq * ST;
    const float4* wr1 = sW + (oq + 16) * ST;
    const float4* wr2 = sW + (oq + 32) * ST;
    const float4* wr3 = sW + (oq + 48) * ST;
    const float4* xr  = sX + (ng * 5) * ST;

    for (int kq = 0; kq < KQ; kq++) {
        float4 w0 = wr0[kq], w1 = wr1[kq], w2 = wr2[kq], w3 = wr3[kq];
#pragma unroll
        for (int i = 0; i < 5; i++) {
            float4 xk = xr[i * ST + kq];
            acc[0][i] = fmaf(w0.x, xk.x, acc[0][i]);
            acc[0][i] = fmaf(w0.y, xk.y, acc[0][i]);
            acc[0][i] = fmaf(w0.z, xk.z, acc[0][i]);
            acc[0][i] = fmaf(w0.w, xk.w, acc[0][i]);
            acc[1][i] = fmaf(w1.x, xk.x, acc[1][i]);
            acc[1][i] = fmaf(w1.y, xk.y, acc[1][i]);
            acc[1][i] = fmaf(w1.z, xk.z, acc[1][i]);
            acc[1][i] = fmaf(w1.w, xk.w, acc[1][i]);
            acc[2][i] = fmaf(w2.x, xk.x, acc[2][i]);
            acc[2][i] = fmaf(w2.y, xk.y, acc[2][i]);
            acc[2][i] = fmaf(w2.z, xk.z, acc[2][i]);
            acc[2][i] = fmaf(w2.w, xk.w, acc[2][i]);
            acc[3][i] = fmaf(w3.x, xk.x, acc[3][i]);
            acc[3][i] = fmaf(w3.y, xk.y, acc[3][i]);
            acc[3][i] = fmaf(w3.z, xk.z, acc[3][i]);
            acc[3][i] = fmaf(w3.w, xk.w, acc[3][i]);
        }
    }

    float ats[4], atd[4];
#pragma unroll
    for (int j = 0; j < 4; j++) {
        ats[j] = att_s[j * 16 + oq];
        atd[j] = att_d[j * 16 + oq];
    }
    float4* __restrict__ as4 = (float4*)g_as;
    float4* __restrict__ ad4 = (float4*)g_ad;

#pragma unroll
    for (int i = 0; i < 5; i++) {
        int n = base + ng * 5 + i;
#pragma unroll
        for (int j = 0; j < 4; j++)
            g_hb[(size_t)n * F + oq + 16 * j] = __float2bfloat16(acc[j][i]);
        float vs0 = acc[0][i] * ats[0], vs1 = acc[1][i] * ats[1];
        float vs2 = acc[2][i] * ats[2], vs3 = acc[3][i] * ats[3];
        float vd0 = acc[0][i] * atd[0], vd1 = acc[1][i] * atd[1];
        float vd2 = acc[2][i] * atd[2], vd3 = acc[3][i] * atd[3];
#pragma unroll
        for (int off = 8; off; off >>= 1) {
            vs0 += __shfl_down_sync(0xffffffffu, vs0, off, 16);
            vs1 += __shfl_down_sync(0xffffffffu, vs1, off, 16);
            vs2 += __shfl_down_sync(0xffffffffu, vs2, off, 16);
            vs3 += __shfl_down_sync(0xffffffffu, vs3, off, 16);
            vd0 += __shfl_down_sync(0xffffffffu, vd0, off, 16);
            vd1 += __shfl_down_sync(0xffffffffu, vd1, off, 16);
            vd2 += __shfl_down_sync(0xffffffffu, vd2, off, 16);
            vd3 += __shfl_down_sync(0xffffffffu, vd3, off, 16);
        }
        if (oq == 0) {
            as4[n] = make_float4(vs0, vs1, vs2, vs3);
            ad4[n] = make_float4(vd0, vd1, vd2, vd3);
        }
    }
}

// ---------------- fused edge pipeline (one-pass softmax) ----------------
__global__ void k_layer(float4* __restrict__ alpha_out,
                        const float* __restrict__ bias, const float* __restrict__ gamma,
                        const float* __restrict__ beta, const float* __restrict__ mu,
                        const float* __restrict__ var) {
    int node = (blockIdx.x * blockDim.x + threadIdx.x) >> 5;
    int lane = threadIdx.x & 31;
    int ro = g_row[node], dg = g_row[node + 1] - ro;
    const float4* __restrict__ as4 = (const float4*)g_as;
    float4* __restrict__ al4 = (float4*)g_al;
    float4 ad = ((const float4*)g_ad)[node];

    float z0 = 0.f, z1 = 0.f, z2 = 0.f, z3 = 0.f;
    for (int i = lane; i < dg; i += 32) {
        int s = g_srcn[ro + i];
        float4 as = as4[s];
        float l0 = as.x + ad.x; l0 = l0 > 0.f ? l0 : NEG * l0;
        float l1 = as.y + ad.y; l1 = l1 > 0.f ? l1 : NEG * l1;
        float l2 = as.z + ad.z; l2 = l2 > 0.f ? l2 : NEG * l2;
        float l3 = as.w + ad.w; l3 = l3 > 0.f ? l3 : NEG * l3;
        float e0 = __expf(l0), e1 = __expf(l1);
        float e2 = __expf(l2), e3 = __expf(l3);
        al4[ro + i] = make_float4(e0, e1, e2, e3);
        z0 += e0; z1 += e1; z2 += e2; z3 += e3;
    }
#pragma unroll
    for (int off = 16; off; off >>= 1) {
        z0 += __shfl_xor_sync(0xffffffffu, z0, off);
        z1 += __shfl_xor_sync(0xffffffffu, z1, off);
        z2 += __shfl_xor_sync(0xffffffffu, z2, off);
        z3 += __shfl_xor_sync(0xffffffffu, z3, off);
    }
    float i0 = 1.f / z0, i1 = 1.f / z1, i2 = 1.f / z2, i3 = 1.f / z3;
    __syncwarp();

    if (alpha_out) {
        for (int i = lane; i < dg; i += 32) {
            int e = g_csr[ro + i];
            float4 ev = al4[ro + i];
            alpha_out[e] = make_float4(ev.x * i0, ev.y * i1, ev.z * i2, ev.w * i3);
        }
    }

    // phase B: lane owns channels {2*lane, 2*lane+1}; h gathered as bf16x2
    float inv = (lane & 16) ? ((lane & 8) ? i3 : i2) : ((lane & 8) ? i1 : i0);
    float ax = 0.f, ay = 0.f;
    int c = lane * 2;
#pragma unroll 4
    for (int i = 0; i < dg; i++) {
        int s = g_srcn[ro + i];              // broadcast
        float4 ev = al4[ro + i];             // broadcast
        float al = (lane & 16) ? ((lane & 8) ? ev.w : ev.z)
                               : ((lane & 8) ? ev.y : ev.x);
        __nv_bfloat162 hb = *(const __nv_bfloat162*)(g_hb + (size_t)s * F + c);
        float2 hv = __bfloat1622float2(hb);
        ax = fmaf(al, hv.x, ax);
        ay = fmaf(al, hv.y, ay);
    }
    ax *= inv; ay *= inv;

    float2 bi = *(const float2*)(bias + c);
    float2 ga = *(const float2*)(gamma + c);
    float2 be = *(const float2*)(beta + c);
    float2 m_ = *(const float2*)(mu + c);
    float2 va = *(const float2*)(var + c);
    float vx = fmaxf(ax + bi.x, 0.f);
    vx = ga.x * (vx - m_.x) * rsqrtf(va.x + EPSbn) + be.x;
    float vy = fmaxf(ay + bi.y, 0.f);
    vy = ga.y * (vy - m_.y) * rsqrtf(va.y + EPSbn) + be.y;
    *(float2*)(g_x + (size_t)node * F + c) = make_float2(vx, vy);
}

// ---------------- head: pool + FC + sigmoid ----------------
__global__ void k_head(const int* __restrict__ batch,
                       const float* __restrict__ fcW, const float* __restrict__ fcb,
                       float* __restrict__ out) {
    __shared__ float sh[4][F];
    int g = blockIdx.x;
    int tid = threadIdx.x;            // 256
    int sub = tid >> 6, c = tid & 63;
    int lo = 0, hi = Nn;
    while (lo < hi) { int m = (lo + hi) >> 1; if (batch[m] < g) lo = m + 1; else hi = m; }
    int r0 = lo;
    lo = 0; hi = Nn;
    while (lo < hi) { int m = (lo + hi) >> 1; if (batch[m] < g + 1) lo = m + 1; else hi = m; }
    int r1 = lo;

    float acc = 0.f;
    for (int n = r0 + sub; n < r1; n += 4) acc += g_x[(size_t)n * F + c];
    sh[sub][c] = acc;
    __syncthreads();
    if (sub == 0) {
        float cnt = fmaxf((float)(r1 - r0), 1.f);
        sh[0][c] = (sh[0][c] + sh[1][c] + sh[2][c] + sh[3][c]) / cnt * fcW[c];
    }
    __syncthreads();
    if (tid == 0) {
        float z = fcb[0];
        for (int i = 0; i < F; i++) z += sh[0][i];
        out[g] = 1.f / (1.f + expf(-z));
    }
}

// ---------------- launch ----------------
extern "C" void kernel_launch(void* const* d_in, const int* in_sizes, int n_in,
                              void* d_out, int out_size) {
    const float* x     = (const float*)d_in[0];
    const int*   ei    = (const int*)  d_in[1];
    const int*   batch = (const int*)  d_in[2];
    const float* P[3][8];
    for (int l = 0; l < 3; l++)
        for (int j = 0; j < 8; j++)
            P[l][j] = (const float*)d_in[3 + l * 8 + j];
    const float* fcW = (const float*)d_in[27];
    const float* fcb = (const float*)d_in[28];

    float* out = (float*)d_out;
    float4* alpha_out = (out_size >= NGr + ET * Hh) ? (float4*)(out + NGr) : nullptr;

    const int TB = 256;
    const int gEdge  = (ET + TB - 1) / TB;
    const int gLayer = Nn / 8;                 // warp per node
    const int gGemm  = Nn / GNB;               // 625

    const int smem0 = (F + GNB) * (IND / 4 + 1) * (int)sizeof(float4);
    const int smem1 = (F + GNB) * (F / 4 + 1) * (int)sizeof(float4);
    cudaFuncSetAttribute(k_gemm<IND>, cudaFuncAttributeMaxDynamicSharedMemorySize, smem0);
    cudaFuncSetAttribute(k_gemm<F>,   cudaFuncAttributeMaxDynamicSharedMemorySize, smem1);

    // CSR build
    k_deg<<<gEdge, TB>>>(ei + Ee);       // dst half only
    k_scan<<<1, 1024>>>();
    k_fill<<<gEdge, TB>>>(ei);

    for (int l = 0; l < 3; l++) {
        if (l == 0) k_gemm<IND><<<gGemm, TB, smem0>>>(x, P[0][0], P[0][1], P[0][2], 0);
        else        k_gemm<F>  <<<gGemm, TB, smem1>>>(x, P[l][0], P[l][1], P[l][2], 1);
        k_layer<<<gLayer, TB>>>(l == 0 ? alpha_out : nullptr,
                                P[l][3], P[l][4], P[l][5], P[l][6], P[l][7]);
    }
    k_head<<<NGr, TB>>>(batch, fcW, fcb, out);
}

// round 13
// speedup vs baseline: 1.6086x; 1.1344x over previous
#include <cuda_runtime.h>
#include <cuda_bf16.h>
#include <math.h>

// ---------------- problem constants ----------------
constexpr int Nn  = 50000;
constexpr int Ee  = 800000;
constexpr int ET  = Ee + Nn;          // 850000
constexpr int Hh  = 4;
constexpr int Cc  = 16;
constexpr int F   = Hh * Cc;          // 64
constexpr int IND = 128;
constexpr int NGr = 128;
constexpr float NEG   = 0.2f;
constexpr float EPSbn = 1e-5f;
constexpr int GNB  = 80;              // gemm nodes per block (50000/80=625)

// ---------------- scratch ----------------
__device__ __nv_bfloat16 g_hb[Nn * F];  // projected features, bf16 (gather side)
__device__ float g_x  [Nn * F];
__device__ float g_as [Nn * Hh];      // float4[Nn]
__device__ float g_ad [Nn * Hh];
__device__ int   g_deg [Nn];          // zero-init; re-zeroed by k_scan each call
__device__ int   g_row [Nn + 1];      // CSR row starts, row[Nn]=ET
__device__ int   g_cur [Nn];
__device__ int2  g_es  [ET];          // (edge id, src node) by CSR position

// ---------------- CSR build ----------------
__global__ void k_deg(const int* __restrict__ dst) {
    int e = blockIdx.x * blockDim.x + threadIdx.x;
    if (e >= ET) return;
    int d = (e < Ee) ? dst[e] : (e - Ee);
    atomicAdd(&g_deg[d], 1);
}

// Single-block scan, int4 per thread (4096-wide tiles).
__global__ void k_scan() {
    __shared__ int wsum[32];
    __shared__ int s_off;
    int tid = threadIdx.x, lane = tid & 31, wid = tid >> 5;
    if (tid == 0) s_off = 0;
    __syncthreads();
    for (int t0 = 0; t0 < Nn; t0 += 4096) {
        int i4 = t0 + tid * 4;
        int4 d = make_int4(0, 0, 0, 0);
        if (i4 < Nn) d = *(const int4*)(g_deg + i4);
        int s = d.x + d.y + d.z + d.w;
        int v = s;
#pragma unroll
        for (int off = 1; off < 32; off <<= 1) {
            int t = __shfl_up_sync(0xffffffffu, v, off);
            if (lane >= off) v += t;
        }
        if (lane == 31) wsum[wid] = v;
        __syncthreads();
        if (wid == 0) {
            int w = wsum[lane];
#pragma unroll
            for (int off = 1; off < 32; off <<= 1) {
                int t = __shfl_up_sync(0xffffffffu, w, off);
                if (lane >= off) w += t;
            }
            wsum[lane] = w;
        }
        __syncthreads();
        int excl = v - s + (wid ? wsum[wid - 1] : 0) + s_off;
        if (i4 < Nn) {
            int4 r = make_int4(excl, excl + d.x, excl + d.x + d.y,
                               excl + d.x + d.y + d.z);
            *(int4*)(g_row + i4) = r;
            *(int4*)(g_cur + i4) = r;
            *(int4*)(g_deg + i4) = make_int4(0, 0, 0, 0);
        }
        __syncthreads();
        if (tid == 0) s_off += wsum[31];
        __syncthreads();
    }
    if (tid == 0) g_row[Nn] = ET;
}

__global__ void k_fill(const int* __restrict__ ei) {
    int e = blockIdx.x * blockDim.x + threadIdx.x;
    if (e >= ET) return;
    int s, d;
    if (e < Ee) { s = ei[e]; d = ei[Ee + e]; }
    else        { s = e - Ee; d = e - Ee; }
    int pos = atomicAdd(&g_cur[d], 1);
    g_es[pos] = make_int2(e, s);        // one 8B store
}

// ---------------- GEMM + fused attention dots ----------------
template <int K>
__global__ void __launch_bounds__(256) k_gemm(
        const float* __restrict__ xparam, const float* __restrict__ W,
        const float* __restrict__ att_s, const float* __restrict__ att_d,
        int use_gx) {
    constexpr int KQ  = K / 4;
    constexpr int ST  = KQ + 1;
    extern __shared__ float4 sm4[];
    float4* sW = sm4;
    float4* sX = sm4 + F * ST;
    const float* __restrict__ xin = use_gx ? (const float*)g_x : xparam;
    const int tid = threadIdx.x;
    const int base = blockIdx.x * GNB;

    for (int i = tid; i < F * KQ; i += 256)
        sW[(i / KQ) * ST + (i % KQ)] = ((const float4*)W)[i];
    const float4* __restrict__ xv = (const float4*)(xin + (size_t)base * K);
    for (int i = tid; i < GNB * KQ; i += 256)
        sX[(i / KQ) * ST + (i % KQ)] = xv[i];
    __syncthreads();

    const int oq = tid & 15, ng = tid >> 4;
    float acc[4][5];
#pragma unroll
    for (int j = 0; j < 4; j++)
#pragma unroll
        for (int i = 0; i < 5; i++) acc[j][i] = 0.f;

    const float4* wr0 = sW + oq * ST;
    const float4* wr1 = sW + (oq + 16) * ST;
    const float4* wr2 = sW + (oq + 32) * ST;
    const float4* wr3 = sW + (oq + 48) * ST;
    const float4* xr  = sX + (ng * 5) * ST;

    for (int kq = 0; kq < KQ; kq++) {
        float4 w0 = wr0[kq], w1 = wr1[kq], w2 = wr2[kq], w3 = wr3[kq];
#pragma unroll
        for (int i = 0; i < 5; i++) {
            float4 xk = xr[i * ST + kq];
            acc[0][i] = fmaf(w0.x, xk.x, acc[0][i]);
            acc[0][i] = fmaf(w0.y, xk.y, acc[0][i]);
            acc[0][i] = fmaf(w0.z, xk.z, acc[0][i]);
            acc[0][i] = fmaf(w0.w, xk.w, acc[0][i]);
            acc[1][i] = fmaf(w1.x, xk.x, acc[1][i]);
            acc[1][i] = fmaf(w1.y, xk.y, acc[1][i]);
            acc[1][i] = fmaf(w1.z, xk.z, acc[1][i]);
            acc[1][i] = fmaf(w1.w, xk.w, acc[1][i]);
            acc[2][i] = fmaf(w2.x, xk.x, acc[2][i]);
            acc[2][i] = fmaf(w2.y, xk.y, acc[2][i]);
            acc[2][i] = fmaf(w2.z, xk.z, acc[2][i]);
            acc[2][i] = fmaf(w2.w, xk.w, acc[2][i]);
            acc[3][i] = fmaf(w3.x, xk.x, acc[3][i]);
            acc[3][i] = fmaf(w3.y, xk.y, acc[3][i]);
            acc[3][i] = fmaf(w3.z, xk.z, acc[3][i]);
            acc[3][i] = fmaf(w3.w, xk.w, acc[3][i]);
        }
    }

    float ats[4], atd[4];
#pragma unroll
    for (int j = 0; j < 4; j++) {
        ats[j] = att_s[j * 16 + oq];
        atd[j] = att_d[j * 16 + oq];
    }
    float4* __restrict__ as4 = (float4*)g_as;
    float4* __restrict__ ad4 = (float4*)g_ad;

#pragma unroll
    for (int i = 0; i < 5; i++) {
        int n = base + ng * 5 + i;
#pragma unroll
        for (int j = 0; j < 4; j++)
            g_hb[(size_t)n * F + oq + 16 * j] = __float2bfloat16(acc[j][i]);
        float vs0 = acc[0][i] * ats[0], vs1 = acc[1][i] * ats[1];
        float vs2 = acc[2][i] * ats[2], vs3 = acc[3][i] * ats[3];
        float vd0 = acc[0][i] * atd[0], vd1 = acc[1][i] * atd[1];
        float vd2 = acc[2][i] * atd[2], vd3 = acc[3][i] * atd[3];
#pragma unroll
        for (int off = 8; off; off >>= 1) {
            vs0 += __shfl_down_sync(0xffffffffu, vs0, off, 16);
            vs1 += __shfl_down_sync(0xffffffffu, vs1, off, 16);
            vs2 += __shfl_down_sync(0xffffffffu, vs2, off, 16);
            vs3 += __shfl_down_sync(0xffffffffu, vs3, off, 16);
            vd0 += __shfl_down_sync(0xffffffffu, vd0, off, 16);
            vd1 += __shfl_down_sync(0xffffffffu, vd1, off, 16);
            vd2 += __shfl_down_sync(0xffffffffu, vd2, off, 16);
            vd3 += __shfl_down_sync(0xffffffffu, vd3, off, 16);
        }
        if (oq == 0) {
            as4[n] = make_float4(vs0, vs1, vs2, vs3);
            ad4[n] = make_float4(vd0, vd1, vd2, vd3);
        }
    }
}

// ---------------- fused edge pipeline: e-values staged in SMEM ----------------
// Warp per node. Phase A computes e once into per-warp smem (cap 128 edges;
// recompute fallback beyond). Phase B: LDS broadcasts + ONE global h-row load
// per edge.
constexpr int DCAP = 128;
__global__ void __launch_bounds__(256) k_layer(
        float4* __restrict__ alpha_out,
        const float* __restrict__ bias, const float* __restrict__ gamma,
        const float* __restrict__ beta, const float* __restrict__ mu,
        const float* __restrict__ var) {
    __shared__ float4 sm_e[8][DCAP];
    __shared__ int    sm_s[8][DCAP];
    int w    = threadIdx.x >> 5;
    int node = (blockIdx.x * blockDim.x + threadIdx.x) >> 5;
    int lane = threadIdx.x & 31;
    int ro = g_row[node], dg = g_row[node + 1] - ro;
    const float4* __restrict__ as4 = (const float4*)g_as;
    float4 ad = ((const float4*)g_ad)[node];

    // phase A: e-values -> smem, accumulate z
    float z0 = 0.f, z1 = 0.f, z2 = 0.f, z3 = 0.f;
    for (int i = lane; i < dg; i += 32) {
        int2 p = g_es[ro + i];
        float4 as = as4[p.y];
        float l0 = as.x + ad.x; l0 = l0 > 0.f ? l0 : NEG * l0;
        float l1 = as.y + ad.y; l1 = l1 > 0.f ? l1 : NEG * l1;
        float l2 = as.z + ad.z; l2 = l2 > 0.f ? l2 : NEG * l2;
        float l3 = as.w + ad.w; l3 = l3 > 0.f ? l3 : NEG * l3;
        float4 e4 = make_float4(__expf(l0), __expf(l1), __expf(l2), __expf(l3));
        if (i < DCAP) { sm_e[w][i] = e4; sm_s[w][i] = p.y; }
        z0 += e4.x; z1 += e4.y; z2 += e4.z; z3 += e4.w;
    }
#pragma unroll
    for (int off = 16; off; off >>= 1) {
        z0 += __shfl_xor_sync(0xffffffffu, z0, off);
        z1 += __shfl_xor_sync(0xffffffffu, z1, off);
        z2 += __shfl_xor_sync(0xffffffffu, z2, off);
        z3 += __shfl_xor_sync(0xffffffffu, z3, off);
    }
    float i0 = 1.f / z0, i1 = 1.f / z1, i2 = 1.f / z2, i3 = 1.f / z3;
    __syncwarp();

    if (alpha_out) {
        for (int i = lane; i < dg; i += 32) {
            int2 p = g_es[ro + i];
            float4 ev;
            if (i < DCAP) ev = sm_e[w][i];
            else {
                float4 as = as4[p.y];
                float l0 = as.x + ad.x; l0 = l0 > 0.f ? l0 : NEG * l0;
                float l1 = as.y + ad.y; l1 = l1 > 0.f ? l1 : NEG * l1;
                float l2 = as.z + ad.z; l2 = l2 > 0.f ? l2 : NEG * l2;
                float l3 = as.w + ad.w; l3 = l3 > 0.f ? l3 : NEG * l3;
                ev = make_float4(__expf(l0), __expf(l1), __expf(l2), __expf(l3));
            }
            alpha_out[p.x] = make_float4(ev.x * i0, ev.y * i1, ev.z * i2, ev.w * i3);
        }
    }

    // phase B: lane owns channels {2*lane, 2*lane+1}; head = lane>>3
    float inv = (lane & 16) ? ((lane & 8) ? i3 : i2) : ((lane & 8) ? i1 : i0);
    float ax = 0.f, ay = 0.f;
    int c = lane * 2;
    int cap = dg < DCAP ? dg : DCAP;
#pragma unroll 4
    for (int i = 0; i < cap; i++) {
        int s = sm_s[w][i];                  // LDS broadcast
        float4 ev = sm_e[w][i];              // LDS.128 broadcast
        float al = (lane & 16) ? ((lane & 8) ? ev.w : ev.z)
                               : ((lane & 8) ? ev.y : ev.x);
        __nv_bfloat162 hb = *(const __nv_bfloat162*)(g_hb + (size_t)s * F + c);
        float2 hv = __bfloat1622float2(hb);
        ax = fmaf(al, hv.x, ax);
        ay = fmaf(al, hv.y, ay);
    }
    for (int i = cap; i < dg; i++) {         // rare: dg > DCAP, recompute
        int2 p = g_es[ro + i];
        float4 as = as4[p.y];
        float l0 = as.x + ad.x; l0 = l0 > 0.f ? l0 : NEG * l0;
        float l1 = as.y + ad.y; l1 = l1 > 0.f ? l1 : NEG * l1;
        float l2 = as.z + ad.z; l2 = l2 > 0.f ? l2 : NEG * l2;
        float l3 = as.w + ad.w; l3 = l3 > 0.f ? l3 : NEG * l3;
        float4 ev = make_float4(__expf(l0), __expf(l1), __expf(l2), __expf(l3));
        float al = (lane & 16) ? ((lane & 8) ? ev.w : ev.z)
                               : ((lane & 8) ? ev.y : ev.x);
        __nv_bfloat162 hb = *(const __nv_bfloat162*)(g_hb + (size_t)p.y * F + c);
        float2 hv = __bfloat1622float2(hb);
        ax = fmaf(al, hv.x, ax);
        ay = fmaf(al, hv.y, ay);
    }
    ax *= inv; ay *= inv;

    float2 bi = *(const float2*)(bias + c);
    float2 ga = *(const float2*)(gamma + c);
    float2 be = *(const float2*)(beta + c);
    float2 m_ = *(const float2*)(mu + c);
    float2 va = *(const float2*)(var + c);
    float vx = fmaxf(ax + bi.x, 0.f);
    vx = ga.x * (vx - m_.x) * rsqrtf(va.x + EPSbn) + be.x;
    float vy = fmaxf(ay + bi.y, 0.f);
    vy = ga.y * (vy - m_.y) * rsqrtf(va.y + EPSbn) + be.y;
    *(float2*)(g_x + (size_t)node * F + c) = make_float2(vx, vy);
}

// ---------------- head: pool + FC + sigmoid ----------------
__global__ void k_head(const int* __restrict__ batch,
                       const float* __restrict__ fcW, const float* __restrict__ fcb,
                       float* __restrict__ out) {
    __shared__ float sh[4][F];
    int g = blockIdx.x;
    int tid = threadIdx.x;            // 256
    int sub = tid >> 6, c = tid & 63;
    int lo = 0, hi = Nn;
    while (lo < hi) { int m = (lo + hi) >> 1; if (batch[m] < g) lo = m + 1; else hi = m; }
    int r0 = lo;
    lo = 0; hi = Nn;
    while (lo < hi) { int m = (lo + hi) >> 1; if (batch[m] < g + 1) lo = m + 1; else hi = m; }
    int r1 = lo;

    float acc = 0.f;
    for (int n = r0 + sub; n < r1; n += 4) acc += g_x[(size_t)n * F + c];
    sh[sub][c] = acc;
    __syncthreads();
    if (sub == 0) {
        float cnt = fmaxf((float)(r1 - r0), 1.f);
        sh[0][c] = (sh[0][c] + sh[1][c] + sh[2][c] + sh[3][c]) / cnt * fcW[c];
    }
    __syncthreads();
    if (tid == 0) {
        float z = fcb[0];
        for (int i = 0; i < F; i++) z += sh[0][i];
        out[g] = 1.f / (1.f + expf(-z));
    }
}

// ---------------- launch ----------------
extern "C" void kernel_launch(void* const* d_in, const int* in_sizes, int n_in,
                              void* d_out, int out_size) {
    const float* x     = (const float*)d_in[0];
    const int*   ei    = (const int*)  d_in[1];
    const int*   batch = (const int*)  d_in[2];
    const float* P[3][8];
    for (int l = 0; l < 3; l++)
        for (int j = 0; j < 8; j++)
            P[l][j] = (const float*)d_in[3 + l * 8 + j];
    const float* fcW = (const float*)d_in[27];
    const float* fcb = (const float*)d_in[28];

    float* out = (float*)d_out;
    float4* alpha_out = (out_size >= NGr + ET * Hh) ? (float4*)(out + NGr) : nullptr;

    const int TB = 256;
    const int gEdge  = (ET + TB - 1) / TB;
    const int gLayer = Nn / 8;                 // warp per node
    const int gGemm  = Nn / GNB;               // 625

    const int smem0 = (F + GNB) * (IND / 4 + 1) * (int)sizeof(float4);
    const int smem1 = (F + GNB) * (F / 4 + 1) * (int)sizeof(float4);
    cudaFuncSetAttribute(k_gemm<IND>, cudaFuncAttributeMaxDynamicSharedMemorySize, smem0);
    cudaFuncSetAttribute(k_gemm<F>,   cudaFuncAttributeMaxDynamicSharedMemorySize, smem1);

    // CSR build
    k_deg<<<gEdge, TB>>>(ei + Ee);       // dst half only
    k_scan<<<1, 1024>>>();
    k_fill<<<gEdge, TB>>>(ei);

    for (int l = 0; l < 3; l++) {
        if (l == 0) k_gemm<IND><<<gGemm, TB, smem0>>>(x, P[0][0], P[0][1], P[0][2], 0);
        else        k_gemm<F>  <<<gGemm, TB, smem1>>>(x, P[l][0], P[l][1], P[l][2], 1);
        k_layer<<<gLayer, TB>>>(l == 0 ? alpha_out : nullptr,
                                P[l][3], P[l][4], P[l][5], P[l][6], P[l][7]);
    }
    k_head<<<NGr, TB>>>(batch, fcW, fcb, out);
}

// round 14
// speedup vs baseline: 1.6122x; 1.0022x over previous
#include <cuda_runtime.h>
#include <cuda_bf16.h>
#include <math.h>

// ---------------- problem constants ----------------
constexpr int Nn  = 50000;
constexpr int Ee  = 800000;
constexpr int ET  = Ee + Nn;          // 850000
constexpr int Hh  = 4;
constexpr int Cc  = 16;
constexpr int F   = Hh * Cc;          // 64
constexpr int IND = 128;
constexpr int NGr = 128;
constexpr float NEG   = 0.2f;
constexpr float EPSbn = 1e-5f;
constexpr int GNB  = 80;              // gemm nodes per block (50000/80=625)

// ---------------- scratch ----------------
__device__ __nv_bfloat16 g_hb[Nn * F];  // projected features, bf16 (gather side)
__device__ float g_x  [Nn * F];
__device__ float g_as [Nn * Hh];      // float4[Nn]
__device__ float g_ad [Nn * Hh];
__device__ int   g_deg [Nn];          // zero-init; re-zeroed by k_scan each call
__device__ int   g_row [Nn + 1];      // CSR row starts, row[Nn]=ET
__device__ int   g_cur [Nn];
__device__ int2  g_es  [ET];          // (edge id, src node) by CSR position

// ---------------- CSR build ----------------
__global__ void k_deg(const int* __restrict__ dst) {
    int e = blockIdx.x * blockDim.x + threadIdx.x;
    if (e >= ET) return;
    int d = (e < Ee) ? dst[e] : (e - Ee);
    atomicAdd(&g_deg[d], 1);
}

// Single-block scan, int4 per thread (4096-wide tiles).
__global__ void k_scan() {
    __shared__ int wsum[32];
    __shared__ int s_off;
    int tid = threadIdx.x, lane = tid & 31, wid = tid >> 5;
    if (tid == 0) s_off = 0;
    __syncthreads();
    for (int t0 = 0; t0 < Nn; t0 += 4096) {
        int i4 = t0 + tid * 4;
        int4 d = make_int4(0, 0, 0, 0);
        if (i4 < Nn) d = *(const int4*)(g_deg + i4);
        int s = d.x + d.y + d.z + d.w;
        int v = s;
#pragma unroll
        for (int off = 1; off < 32; off <<= 1) {
            int t = __shfl_up_sync(0xffffffffu, v, off);
            if (lane >= off) v += t;
        }
        if (lane == 31) wsum[wid] = v;
        __syncthreads();
        if (wid == 0) {
            int w = wsum[lane];
#pragma unroll
            for (int off = 1; off < 32; off <<= 1) {
                int t = __shfl_up_sync(0xffffffffu, w, off);
                if (lane >= off) w += t;
            }
            wsum[lane] = w;
        }
        __syncthreads();
        int excl = v - s + (wid ? wsum[wid - 1] : 0) + s_off;
        if (i4 < Nn) {
            int4 r = make_int4(excl, excl + d.x, excl + d.x + d.y,
                               excl + d.x + d.y + d.z);
            *(int4*)(g_row + i4) = r;
            *(int4*)(g_cur + i4) = r;
            *(int4*)(g_deg + i4) = make_int4(0, 0, 0, 0);
        }
        __syncthreads();
        if (tid == 0) s_off += wsum[31];
        __syncthreads();
    }
    if (tid == 0) g_row[Nn] = ET;
}

__global__ void k_fill(const int* __restrict__ ei) {
    int e = blockIdx.x * blockDim.x + threadIdx.x;
    if (e >= ET) return;
    int s, d;
    if (e < Ee) { s = ei[e]; d = ei[Ee + e]; }
    else        { s = e - Ee; d = e - Ee; }
    int pos = atomicAdd(&g_cur[d], 1);
    g_es[pos] = make_int2(e, s);        // one 8B store
}

// ---------------- GEMM + fused attention dots ----------------
// float4 smem staging + LDS.128; kq loop unrolled x4 so ptxas can pipeline
// LDS across iterations (hides 29cyc LDS latency at low occupancy).
template <int K>
__global__ void k_gemm(
        const float* __restrict__ xparam, const float* __restrict__ W,
        const float* __restrict__ att_s, const float* __restrict__ att_d,
        int use_gx) {
    constexpr int KQ  = K / 4;
    constexpr int ST  = KQ + 1;
    extern __shared__ float4 sm4[];
    float4* sW = sm4;
    float4* sX = sm4 + F * ST;
    const float* __restrict__ xin = use_gx ? (const float*)g_x : xparam;
    const int tid = threadIdx.x;
    const int base = blockIdx.x * GNB;

    for (int i = tid; i < F * KQ; i += 256)
        sW[(i / KQ) * ST + (i % KQ)] = ((const float4*)W)[i];
    const float4* __restrict__ xv = (const float4*)(xin + (size_t)base * K);
    for (int i = tid; i < GNB * KQ; i += 256)
        sX[(i / KQ) * ST + (i % KQ)] = xv[i];
    __syncthreads();

    const int oq = tid & 15, ng = tid >> 4;
    float acc[4][5];
#pragma unroll
    for (int j = 0; j < 4; j++)
#pragma unroll
        for (int i = 0; i < 5; i++) acc[j][i] = 0.f;

    const float4* wr0 = sW + oq * ST;
    const float4* wr1 = sW + (oq + 16) * ST;
    const float4* wr2 = sW + (oq + 32) * ST;
    const float4* wr3 = sW + (oq + 48) * ST;
    const float4* xr  = sX + (ng * 5) * ST;

#pragma unroll 4
    for (int kq = 0; kq < KQ; kq++) {
        float4 w0 = wr0[kq], w1 = wr1[kq], w2 = wr2[kq], w3 = wr3[kq];
#pragma unroll
        for (int i = 0; i < 5; i++) {
            float4 xk = xr[i * ST + kq];
            acc[0][i] = fmaf(w0.x, xk.x, acc[0][i]);
            acc[0][i] = fmaf(w0.y, xk.y, acc[0][i]);
            acc[0][i] = fmaf(w0.z, xk.z, acc[0][i]);
            acc[0][i] = fmaf(w0.w, xk.w, acc[0][i]);
            acc[1][i] = fmaf(w1.x, xk.x, acc[1][i]);
            acc[1][i] = fmaf(w1.y, xk.y, acc[1][i]);
            acc[1][i] = fmaf(w1.z, xk.z, acc[1][i]);
            acc[1][i] = fmaf(w1.w, xk.w, acc[1][i]);
            acc[2][i] = fmaf(w2.x, xk.x, acc[2][i]);
            acc[2][i] = fmaf(w2.y, xk.y, acc[2][i]);
            acc[2][i] = fmaf(w2.z, xk.z, acc[2][i]);
            acc[2][i] = fmaf(w2.w, xk.w, acc[2][i]);
            acc[3][i] = fmaf(w3.x, xk.x, acc[3][i]);
            acc[3][i] = fmaf(w3.y, xk.y, acc[3][i]);
            acc[3][i] = fmaf(w3.z, xk.z, acc[3][i]);
            acc[3][i] = fmaf(w3.w, xk.w, acc[3][i]);
        }
    }

    float ats[4], atd[4];
#pragma unroll
    for (int j = 0; j < 4; j++) {
        ats[j] = att_s[j * 16 + oq];
        atd[j] = att_d[j * 16 + oq];
    }
    float4* __restrict__ as4 = (float4*)g_as;
    float4* __restrict__ ad4 = (float4*)g_ad;

#pragma unroll
    for (int i = 0; i < 5; i++) {
        int n = base + ng * 5 + i;
#pragma unroll
        for (int j = 0; j < 4; j++)
            g_hb[(size_t)n * F + oq + 16 * j] = __float2bfloat16(acc[j][i]);
        float vs0 = acc[0][i] * ats[0], vs1 = acc[1][i] * ats[1];
        float vs2 = acc[2][i] * ats[2], vs3 = acc[3][i] * ats[3];
        float vd0 = acc[0][i] * atd[0], vd1 = acc[1][i] * atd[1];
        float vd2 = acc[2][i] * atd[2], vd3 = acc[3][i] * atd[3];
#pragma unroll
        for (int off = 8; off; off >>= 1) {
            vs0 += __shfl_down_sync(0xffffffffu, vs0, off, 16);
            vs1 += __shfl_down_sync(0xffffffffu, vs1, off, 16);
            vs2 += __shfl_down_sync(0xffffffffu, vs2, off, 16);
            vs3 += __shfl_down_sync(0xffffffffu, vs3, off, 16);
            vd0 += __shfl_down_sync(0xffffffffu, vd0, off, 16);
            vd1 += __shfl_down_sync(0xffffffffu, vd1, off, 16);
            vd2 += __shfl_down_sync(0xffffffffu, vd2, off, 16);
            vd3 += __shfl_down_sync(0xffffffffu, vd3, off, 16);
        }
        if (oq == 0) {
            as4[n] = make_float4(vs0, vs1, vs2, vs3);
            ad4[n] = make_float4(vd0, vd1, vd2, vd3);
        }
    }
}

// ---------------- fused edge pipeline: e-values staged in SMEM ----------------
constexpr int DCAP = 128;
__global__ void __launch_bounds__(256) k_layer(
        float4* __restrict__ alpha_out,
        const float* __restrict__ bias, const float* __restrict__ gamma,
        const float* __restrict__ beta, const float* __restrict__ mu,
        const float* __restrict__ var) {
    __shared__ float4 sm_e[8][DCAP];
    __shared__ int    sm_s[8][DCAP];
    int w    = threadIdx.x >> 5;
    int node = (blockIdx.x * blockDim.x + threadIdx.x) >> 5;
    int lane = threadIdx.x & 31;
    int ro = g_row[node], dg = g_row[node + 1] - ro;
    const float4* __restrict__ as4 = (const float4*)g_as;
    float4 ad = ((const float4*)g_ad)[node];

    // phase A: e-values -> smem, accumulate z
    float z0 = 0.f, z1 = 0.f, z2 = 0.f, z3 = 0.f;
    for (int i = lane; i < dg; i += 32) {
        int2 p = g_es[ro + i];
        float4 as = as4[p.y];
        float l0 = as.x + ad.x; l0 = l0 > 0.f ? l0 : NEG * l0;
        float l1 = as.y + ad.y; l1 = l1 > 0.f ? l1 : NEG * l1;
        float l2 = as.z + ad.z; l2 = l2 > 0.f ? l2 : NEG * l2;
        float l3 = as.w + ad.w; l3 = l3 > 0.f ? l3 : NEG * l3;
        float4 e4 = make_float4(__expf(l0), __expf(l1), __expf(l2), __expf(l3));
        if (i < DCAP) { sm_e[w][i] = e4; sm_s[w][i] = p.y; }
        z0 += e4.x; z1 += e4.y; z2 += e4.z; z3 += e4.w;
    }
#pragma unroll
    for (int off = 16; off; off >>= 1) {
        z0 += __shfl_xor_sync(0xffffffffu, z0, off);
        z1 += __shfl_xor_sync(0xffffffffu, z1, off);
        z2 += __shfl_xor_sync(0xffffffffu, z2, off);
        z3 += __shfl_xor_sync(0xffffffffu, z3, off);
    }
    float i0 = 1.f / z0, i1 = 1.f / z1, i2 = 1.f / z2, i3 = 1.f / z3;
    __syncwarp();

    if (alpha_out) {
        for (int i = lane; i < dg; i += 32) {
            int2 p = g_es[ro + i];
            float4 ev;
            if (i < DCAP) ev = sm_e[w][i];
            else {
                float4 as = as4[p.y];
                float l0 = as.x + ad.x; l0 = l0 > 0.f ? l0 : NEG * l0;
                float l1 = as.y + ad.y; l1 = l1 > 0.f ? l1 : NEG * l1;
                float l2 = as.z + ad.z; l2 = l2 > 0.f ? l2 : NEG * l2;
                float l3 = as.w + ad.w; l3 = l3 > 0.f ? l3 : NEG * l3;
                ev = make_float4(__expf(l0), __expf(l1), __expf(l2), __expf(l3));
            }
            alpha_out[p.x] = make_float4(ev.x * i0, ev.y * i1, ev.z * i2, ev.w * i3);
        }
    }

    // phase B: lane owns channels {2*lane, 2*lane+1}; head = lane>>3
    float inv = (lane & 16) ? ((lane & 8) ? i3 : i2) : ((lane & 8) ? i1 : i0);
    float ax = 0.f, ay = 0.f;
    int c = lane * 2;
    int cap = dg < DCAP ? dg : DCAP;
#pragma unroll 8
    for (int i = 0; i < cap; i++) {
        int s = sm_s[w][i];                  // LDS broadcast
        float4 ev = sm_e[w][i];              // LDS.128 broadcast
        float al = (lane & 16) ? ((lane & 8) ? ev.w : ev.z)
                               : ((lane & 8) ? ev.y : ev.x);
        __nv_bfloat162 hb = *(const __nv_bfloat162*)(g_hb + (size_t)s * F + c);
        float2 hv = __bfloat1622float2(hb);
        ax = fmaf(al, hv.x, ax);
        ay = fmaf(al, hv.y, ay);
    }
    for (int i = cap; i < dg; i++) {         // rare: dg > DCAP, recompute
        int2 p = g_es[ro + i];
        float4 as = as4[p.y];
        float l0 = as.x + ad.x; l0 = l0 > 0.f ? l0 : NEG * l0;
        float l1 = as.y + ad.y; l1 = l1 > 0.f ? l1 : NEG * l1;
        float l2 = as.z + ad.z; l2 = l2 > 0.f ? l2 : NEG * l2;
        float l3 = as.w + ad.w; l3 = l3 > 0.f ? l3 : NEG * l3;
        float4 ev = make_float4(__expf(l0), __expf(l1), __expf(l2), __expf(l3));
        float al = (lane & 16) ? ((lane & 8) ? ev.w : ev.z)
                               : ((lane & 8) ? ev.y : ev.x);
        __nv_bfloat162 hb = *(const __nv_bfloat162*)(g_hb + (size_t)p.y * F + c);
        float2 hv = __bfloat1622float2(hb);
        ax = fmaf(al, hv.x, ax);
        ay = fmaf(al, hv.y, ay);
    }
    ax *= inv; ay *= inv;

    float2 bi = *(const float2*)(bias + c);
    float2 ga = *(const float2*)(gamma + c);
    float2 be = *(const float2*)(beta + c);
    float2 m_ = *(const float2*)(mu + c);
    float2 va = *(const float2*)(var + c);
    float vx = fmaxf(ax + bi.x, 0.f);
    vx = ga.x * (vx - m_.x) * rsqrtf(va.x + EPSbn) + be.x;
    float vy = fmaxf(ay + bi.y, 0.f);
    vy = ga.y * (vy - m_.y) * rsqrtf(va.y + EPSbn) + be.y;
    *(float2*)(g_x + (size_t)node * F + c) = make_float2(vx, vy);
}

// ---------------- head: pool + FC + sigmoid ----------------
__global__ void k_head(const int* __restrict__ batch,
                       const float* __restrict__ fcW, const float* __restrict__ fcb,
                       float* __restrict__ out) {
    __shared__ float sh[4][F];
    int g = blockIdx.x;
    int tid = threadIdx.x;            // 256
    int sub = tid >> 6, c = tid & 63;
    int lo = 0, hi = Nn;
    while (lo < hi) { int m = (lo + hi) >> 1; if (batch[m] < g) lo = m + 1; else hi = m; }
    int r0 = lo;
    lo = 0; hi = Nn;
    while (lo < hi) { int m = (lo + hi) >> 1; if (batch[m] < g + 1) lo = m + 1; else hi = m; }
    int r1 = lo;

    float acc = 0.f;
    for (int n = r0 + sub; n < r1; n += 4) acc += g_x[(size_t)n * F + c];
    sh[sub][c] = acc;
    __syncthreads();
    if (sub == 0) {
        float cnt = fmaxf((float)(r1 - r0), 1.f);
        sh[0][c] = (sh[0][c] + sh[1][c] + sh[2][c] + sh[3][c]) / cnt * fcW[c];
    }
    __syncthreads();
    if (tid == 0) {
        float z = fcb[0];
        for (int i = 0; i < F; i++) z += sh[0][i];
        out[g] = 1.f / (1.f + expf(-z));
    }
}

// ---------------- launch ----------------
extern "C" void kernel_launch(void* const* d_in, const int* in_sizes, int n_in,
                              void* d_out, int out_size) {
    const float* x     = (const float*)d_in[0];
    const int*   ei    = (const int*)  d_in[1];
    const int*   batch = (const int*)  d_in[2];
    const float* P[3][8];
    for (int l = 0; l < 3; l++)
        for (int j = 0; j < 8; j++)
            P[l][j] = (const float*)d_in[3 + l * 8 + j];
    const float* fcW = (const float*)d_in[27];
    const float* fcb = (const float*)d_in[28];

    float* out = (float*)d_out;
    float4* alpha_out = (out_size >= NGr + ET * Hh) ? (float4*)(out + NGr) : nullptr;

    const int TB = 256;
    const int gEdge  = (ET + TB - 1) / TB;
    const int gLayer = Nn / 8;                 // warp per node
    const int gGemm  = Nn / GNB;               // 625

    const int smem0 = (F + GNB) * (IND / 4 + 1) * (int)sizeof(float4);
    const int smem1 = (F + GNB) * (F / 4 + 1) * (int)sizeof(float4);
    cudaFuncSetAttribute(k_gemm<IND>, cudaFuncAttributeMaxDynamicSharedMemorySize, smem0);
    cudaFuncSetAttribute(k_gemm<F>,   cudaFuncAttributeMaxDynamicSharedMemorySize, smem1);

    // CSR build
    k_deg<<<gEdge, TB>>>(ei + Ee);       // dst half only
    k_scan<<<1, 1024>>>();
    k_fill<<<gEdge, TB>>>(ei);

    for (int l = 0; l < 3; l++) {
        if (l == 0) k_gemm<IND><<<gGemm, TB, smem0>>>(x, P[0][0], P[0][1], P[0][2], 0);
        else        k_gemm<F>  <<<gGemm, TB, smem1>>>(x, P[l][0], P[l][1], P[l][2], 1);
        k_layer<<<gLayer, TB>>>(l == 0 ? alpha_out : nullptr,
                                P[l][3], P[l][4], P[l][5], P[l][6], P[l][7]);
    }
    k_head<<<NGr, TB>>>(batch, fcW, fcb, out);
}

// round 15
// speedup vs baseline: 1.8022x; 1.1178x over previous
#include <cuda_runtime.h>
#include <cuda_bf16.h>
#include <math.h>

// ---------------- problem constants ----------------
constexpr int Nn  = 50000;
constexpr int Ee  = 800000;
constexpr int ET  = Ee + Nn;          // 850000
constexpr int Hh  = 4;
constexpr int Cc  = 16;
constexpr int F   = Hh * Cc;          // 64
constexpr int IND = 128;
constexpr int NGr = 128;
constexpr float NEG   = 0.2f;
constexpr float EPSbn = 1e-5f;

// ---------------- scratch ----------------
__device__ __nv_bfloat16 g_hb[Nn * F];  // projected features, bf16 (gather side)
__device__ float g_x  [Nn * F];
__device__ float g_as [Nn * Hh];      // float4[Nn]
__device__ float g_ad [Nn * Hh];
__device__ int   g_deg [Nn];          // zero-init; re-zeroed by k_scan each call
__device__ int   g_row [Nn + 1];      // CSR row starts, row[Nn]=ET
__device__ int   g_cur [Nn];
__device__ int2  g_es  [ET];          // (edge id, src node) by CSR position

__device__ __forceinline__ float tf32r(float f) {
    float r;
    asm("cvt.rna.tf32.f32 %0, %1;" : "=f"(r) : "f"(f));
    return r;
}

// ---------------- CSR build ----------------
__global__ void k_deg(const int* __restrict__ dst) {
    int e = blockIdx.x * blockDim.x + threadIdx.x;
    if (e >= ET) return;
    int d = (e < Ee) ? dst[e] : (e - Ee);
    atomicAdd(&g_deg[d], 1);
}

__global__ void k_scan() {
    __shared__ int wsum[32];
    __shared__ int s_off;
    int tid = threadIdx.x, lane = tid & 31, wid = tid >> 5;
    if (tid == 0) s_off = 0;
    __syncthreads();
    for (int t0 = 0; t0 < Nn; t0 += 4096) {
        int i4 = t0 + tid * 4;
        int4 d = make_int4(0, 0, 0, 0);
        if (i4 < Nn) d = *(const int4*)(g_deg + i4);
        int s = d.x + d.y + d.z + d.w;
        int v = s;
#pragma unroll
        for (int off = 1; off < 32; off <<= 1) {
            int t = __shfl_up_sync(0xffffffffu, v, off);
            if (lane >= off) v += t;
        }
        if (lane == 31) wsum[wid] = v;
        __syncthreads();
        if (wid == 0) {
            int w = wsum[lane];
#pragma unroll
            for (int off = 1; off < 32; off <<= 1) {
                int t = __shfl_up_sync(0xffffffffu, w, off);
                if (lane >= off) w += t;
            }
            wsum[lane] = w;
        }
        __syncthreads();
        int excl = v - s + (wid ? wsum[wid - 1] : 0) + s_off;
        if (i4 < Nn) {
            int4 r = make_int4(excl, excl + d.x, excl + d.x + d.y,
                               excl + d.x + d.y + d.z);
            *(int4*)(g_row + i4) = r;
            *(int4*)(g_cur + i4) = r;
            *(int4*)(g_deg + i4) = make_int4(0, 0, 0, 0);
        }
        __syncthreads();
        if (tid == 0) s_off += wsum[31];
        __syncthreads();
    }
    if (tid == 0) g_row[Nn] = ET;
}

__global__ void k_fill(const int* __restrict__ ei) {
    int e = blockIdx.x * blockDim.x + threadIdx.x;
    if (e >= ET) return;
    int s, d;
    if (e < Ee) { s = ei[e]; d = ei[Ee + e]; }
    else        { s = e - Ee; d = e - Ee; }
    int pos = atomicAdd(&g_cur[d], 1);
    g_es[pos] = make_int2(e, s);
}

// ---------------- GEMM via mma.sync tf32 + fused attention dots ----------------
// 8 warps x 16 nodes = 128 nodes/block. C[m16,n8] tiles: 8 n-tiles cover F=64.
// Smem rows padded to K+4 floats (16B-aligned, conflict-free fragment LDS).
template <int K>
__global__ void k_gemm(const float* __restrict__ xparam,
                       const float* __restrict__ W,
                       const float* __restrict__ att_s,
                       const float* __restrict__ att_d, int use_gx) {
    constexpr int KQ = K / 4;
    constexpr int KP = K + 4;
    extern __shared__ float smf[];
    float* sX = smf;              // [128][KP]
    float* sW = smf + 128 * KP;   // [64][KP]
    const float* __restrict__ xin = use_gx ? (const float*)g_x : xparam;
    const int tid = threadIdx.x;
    const int base = blockIdx.x * 128;

    for (int i = tid; i < F * KQ; i += 256) {
        int r = i / KQ, c4 = i % KQ;
        float4 w = ((const float4*)W)[i];
        w.x = tf32r(w.x); w.y = tf32r(w.y); w.z = tf32r(w.z); w.w = tf32r(w.w);
        *(float4*)(sW + r * KP + c4 * 4) = w;
    }
    for (int i = tid; i < 128 * KQ; i += 256) {
        int r = i / KQ, c4 = i % KQ;
        int n = base + r;
        float4 v = make_float4(0.f, 0.f, 0.f, 0.f);
        if (n < Nn) v = ((const float4*)xin)[(size_t)n * KQ + c4];
        v.x = tf32r(v.x); v.y = tf32r(v.y); v.z = tf32r(v.z); v.w = tf32r(v.w);
        *(float4*)(sX + r * KP + c4 * 4) = v;
    }
    __syncthreads();

    const int warp = tid >> 5, lane = tid & 31;
    const int grp = lane >> 2, tig = lane & 3;
    const float* xa = sX + (warp * 16) * KP;

    float c[8][4];
#pragma unroll
    for (int nt = 0; nt < 8; nt++)
#pragma unroll
        for (int j = 0; j < 4; j++) c[nt][j] = 0.f;

    for (int kk = 0; kk < K; kk += 8) {
        unsigned a0 = __float_as_uint(xa[grp * KP + kk + tig]);
        unsigned a1 = __float_as_uint(xa[(grp + 8) * KP + kk + tig]);
        unsigned a2 = __float_as_uint(xa[grp * KP + kk + tig + 4]);
        unsigned a3 = __float_as_uint(xa[(grp + 8) * KP + kk + tig + 4]);
#pragma unroll
        for (int nt = 0; nt < 8; nt++) {
            unsigned b0 = __float_as_uint(sW[(nt * 8 + grp) * KP + kk + tig]);
            unsigned b1 = __float_as_uint(sW[(nt * 8 + grp) * KP + kk + tig + 4]);
            asm volatile(
                "mma.sync.aligned.m16n8k8.row.col.f32.tf32.tf32.f32 "
                "{%0,%1,%2,%3}, {%4,%5,%6,%7}, {%8,%9}, {%0,%1,%2,%3};\n"
                : "+f"(c[nt][0]), "+f"(c[nt][1]), "+f"(c[nt][2]), "+f"(c[nt][3])
                : "r"(a0), "r"(a1), "r"(a2), "r"(a3), "r"(b0), "r"(b1));
        }
    }

    // Epilogue: bf16 h store + per-head attention dots (fp32 acc).
    // Thread holds channels {nt*8 + 2*tig, +1} for nodes n1 (rows c0,c1) and
    // n2 = n1+8 (rows c2,c3). Head of n-tile nt is nt>>1.
    int n1 = base + warp * 16 + grp;
    int n2 = n1 + 8;
    float vs1[4] = {0, 0, 0, 0}, vd1[4] = {0, 0, 0, 0};
    float vs2[4] = {0, 0, 0, 0}, vd2[4] = {0, 0, 0, 0};
#pragma unroll
    for (int nt = 0; nt < 8; nt++) {
        int ch0 = nt * 8 + 2 * tig;
        float as0 = att_s[ch0], as1 = att_s[ch0 + 1];
        float ad0 = att_d[ch0], ad1 = att_d[ch0 + 1];
        int h = nt >> 1;
        vs1[h] += c[nt][0] * as0 + c[nt][1] * as1;
        vd1[h] += c[nt][0] * ad0 + c[nt][1] * ad1;
        vs2[h] += c[nt][2] * as0 + c[nt][3] * as1;
        vd2[h] += c[nt][2] * ad0 + c[nt][3] * ad1;
        if (n1 < Nn)
            *(__nv_bfloat162*)(g_hb + (size_t)n1 * F + ch0) =
                __floats2bfloat162_rn(c[nt][0], c[nt][1]);
        if (n2 < Nn)
            *(__nv_bfloat162*)(g_hb + (size_t)n2 * F + ch0) =
                __floats2bfloat162_rn(c[nt][2], c[nt][3]);
    }
#pragma unroll
    for (int h = 0; h < 4; h++) {
        vs1[h] += __shfl_xor_sync(0xffffffffu, vs1[h], 1);
        vs1[h] += __shfl_xor_sync(0xffffffffu, vs1[h], 2);
        vd1[h] += __shfl_xor_sync(0xffffffffu, vd1[h], 1);
        vd1[h] += __shfl_xor_sync(0xffffffffu, vd1[h], 2);
        vs2[h] += __shfl_xor_sync(0xffffffffu, vs2[h], 1);
        vs2[h] += __shfl_xor_sync(0xffffffffu, vs2[h], 2);
        vd2[h] += __shfl_xor_sync(0xffffffffu, vd2[h], 1);
        vd2[h] += __shfl_xor_sync(0xffffffffu, vd2[h], 2);
    }
    if (tig == 0) {
        float4* __restrict__ as4 = (float4*)g_as;
        float4* __restrict__ ad4 = (float4*)g_ad;
        if (n1 < Nn) {
            as4[n1] = make_float4(vs1[0], vs1[1], vs1[2], vs1[3]);
            ad4[n1] = make_float4(vd1[0], vd1[1], vd1[2], vd1[3]);
        }
        if (n2 < Nn) {
            as4[n2] = make_float4(vs2[0], vs2[1], vs2[2], vs2[3]);
            ad4[n2] = make_float4(vd2[0], vd2[1], vd2[2], vd2[3]);
        }
    }
}

// ---------------- fused edge pipeline: e-values staged in SMEM ----------------
constexpr int DCAP = 128;
__global__ void __launch_bounds__(256) k_layer(
        float4* __restrict__ alpha_out,
        const float* __restrict__ bias, const float* __restrict__ gamma,
        const float* __restrict__ beta, const float* __restrict__ mu,
        const float* __restrict__ var) {
    __shared__ float4 sm_e[8][DCAP];
    __shared__ int    sm_s[8][DCAP];
    int w    = threadIdx.x >> 5;
    int node = (blockIdx.x * blockDim.x + threadIdx.x) >> 5;
    int lane = threadIdx.x & 31;
    int ro = g_row[node], dg = g_row[node + 1] - ro;
    const float4* __restrict__ as4 = (const float4*)g_as;
    float4 ad = ((const float4*)g_ad)[node];

    float z0 = 0.f, z1 = 0.f, z2 = 0.f, z3 = 0.f;
    for (int i = lane; i < dg; i += 32) {
        int2 p = g_es[ro + i];
        float4 as = as4[p.y];
        float l0 = as.x + ad.x; l0 = l0 > 0.f ? l0 : NEG * l0;
        float l1 = as.y + ad.y; l1 = l1 > 0.f ? l1 : NEG * l1;
        float l2 = as.z + ad.z; l2 = l2 > 0.f ? l2 : NEG * l2;
        float l3 = as.w + ad.w; l3 = l3 > 0.f ? l3 : NEG * l3;
        float4 e4 = make_float4(__expf(l0), __expf(l1), __expf(l2), __expf(l3));
        if (i < DCAP) { sm_e[w][i] = e4; sm_s[w][i] = p.y; }
        z0 += e4.x; z1 += e4.y; z2 += e4.z; z3 += e4.w;
    }
#pragma unroll
    for (int off = 16; off; off >>= 1) {
        z0 += __shfl_xor_sync(0xffffffffu, z0, off);
        z1 += __shfl_xor_sync(0xffffffffu, z1, off);
        z2 += __shfl_xor_sync(0xffffffffu, z2, off);
        z3 += __shfl_xor_sync(0xffffffffu, z3, off);
    }
    float i0 = 1.f / z0, i1 = 1.f / z1, i2 = 1.f / z2, i3 = 1.f / z3;
    __syncwarp();

    if (alpha_out) {
        for (int i = lane; i < dg; i += 32) {
            int2 p = g_es[ro + i];
            float4 ev;
            if (i < DCAP) ev = sm_e[w][i];
            else {
                float4 as = as4[p.y];
                float l0 = as.x + ad.x; l0 = l0 > 0.f ? l0 : NEG * l0;
                float l1 = as.y + ad.y; l1 = l1 > 0.f ? l1 : NEG * l1;
                float l2 = as.z + ad.z; l2 = l2 > 0.f ? l2 : NEG * l2;
                float l3 = as.w + ad.w; l3 = l3 > 0.f ? l3 : NEG * l3;
                ev = make_float4(__expf(l0), __expf(l1), __expf(l2), __expf(l3));
            }
            alpha_out[p.x] = make_float4(ev.x * i0, ev.y * i1, ev.z * i2, ev.w * i3);
        }
    }

    float inv = (lane & 16) ? ((lane & 8) ? i3 : i2) : ((lane & 8) ? i1 : i0);
    float ax = 0.f, ay = 0.f;
    int c = lane * 2;
    int cap = dg < DCAP ? dg : DCAP;
#pragma unroll 8
    for (int i = 0; i < cap; i++) {
        int s = sm_s[w][i];
        float4 ev = sm_e[w][i];
        float al = (lane & 16) ? ((lane & 8) ? ev.w : ev.z)
                               : ((lane & 8) ? ev.y : ev.x);
        __nv_bfloat162 hb = *(const __nv_bfloat162*)(g_hb + (size_t)s * F + c);
        float2 hv = __bfloat1622float2(hb);
        ax = fmaf(al, hv.x, ax);
        ay = fmaf(al, hv.y, ay);
    }
    for (int i = cap; i < dg; i++) {
        int2 p = g_es[ro + i];
        float4 as = as4[p.y];
        float l0 = as.x + ad.x; l0 = l0 > 0.f ? l0 : NEG * l0;
        float l1 = as.y + ad.y; l1 = l1 > 0.f ? l1 : NEG * l1;
        float l2 = as.z + ad.z; l2 = l2 > 0.f ? l2 : NEG * l2;
        float l3 = as.w + ad.w; l3 = l3 > 0.f ? l3 : NEG * l3;
        float4 ev = make_float4(__expf(l0), __expf(l1), __expf(l2), __expf(l3));
        float al = (lane & 16) ? ((lane & 8) ? ev.w : ev.z)
                               : ((lane & 8) ? ev.y : ev.x);
        __nv_bfloat162 hb = *(const __nv_bfloat162*)(g_hb + (size_t)p.y * F + c);
        float2 hv = __bfloat1622float2(hb);
        ax = fmaf(al, hv.x, ax);
        ay = fmaf(al, hv.y, ay);
    }
    ax *= inv; ay *= inv;

    float2 bi = *(const float2*)(bias + c);
    float2 ga = *(const float2*)(gamma + c);
    float2 be = *(const float2*)(beta + c);
    float2 m_ = *(const float2*)(mu + c);
    float2 va = *(const float2*)(var + c);
    float vx = fmaxf(ax + bi.x, 0.f);
    vx = ga.x * (vx - m_.x) * rsqrtf(va.x + EPSbn) + be.x;
    float vy = fmaxf(ay + bi.y, 0.f);
    vy = ga.y * (vy - m_.y) * rsqrtf(va.y + EPSbn) + be.y;
    *(float2*)(g_x + (size_t)node * F + c) = make_float2(vx, vy);
}

// ---------------- head: pool + FC + sigmoid ----------------
__global__ void k_head(const int* __restrict__ batch,
                       const float* __restrict__ fcW, const float* __restrict__ fcb,
                       float* __restrict__ out) {
    __shared__ float sh[4][F];
    int g = blockIdx.x;
    int tid = threadIdx.x;
    int sub = tid >> 6, c = tid & 63;
    int lo = 0, hi = Nn;
    while (lo < hi) { int m = (lo + hi) >> 1; if (batch[m] < g) lo = m + 1; else hi = m; }
    int r0 = lo;
    lo = 0; hi = Nn;
    while (lo < hi) { int m = (lo + hi) >> 1; if (batch[m] < g + 1) lo = m + 1; else hi = m; }
    int r1 = lo;

    float acc = 0.f;
    for (int n = r0 + sub; n < r1; n += 4) acc += g_x[(size_t)n * F + c];
    sh[sub][c] = acc;
    __syncthreads();
    if (sub == 0) {
        float cnt = fmaxf((float)(r1 - r0), 1.f);
        sh[0][c] = (sh[0][c] + sh[1][c] + sh[2][c] + sh[3][c]) / cnt * fcW[c];
    }
    __syncthreads();
    if (tid == 0) {
        float z = fcb[0];
        for (int i = 0; i < F; i++) z += sh[0][i];
        out[g] = 1.f / (1.f + expf(-z));
    }
}

// ---------------- launch ----------------
extern "C" void kernel_launch(void* const* d_in, const int* in_sizes, int n_in,
                              void* d_out, int out_size) {
    const float* x     = (const float*)d_in[0];
    const int*   ei    = (const int*)  d_in[1];
    const int*   batch = (const int*)  d_in[2];
    const float* P[3][8];
    for (int l = 0; l < 3; l++)
        for (int j = 0; j < 8; j++)
            P[l][j] = (const float*)d_in[3 + l * 8 + j];
    const float* fcW = (const float*)d_in[27];
    const float* fcb = (const float*)d_in[28];

    float* out = (float*)d_out;
    float4* alpha_out = (out_size >= NGr + ET * Hh) ? (float4*)(out + NGr) : nullptr;

    const int TB = 256;
    const int gEdge  = (ET + TB - 1) / TB;
    const int gLayer = Nn / 8;                     // warp per node
    const int gGemm  = (Nn + 127) / 128;           // 391

    const int smem0 = (128 + F) * (IND + 4) * (int)sizeof(float);  // ~101 KB
    const int smem1 = (128 + F) * (F + 4) * (int)sizeof(float);    // ~52 KB
    cudaFuncSetAttribute(k_gemm<IND>, cudaFuncAttributeMaxDynamicSharedMemorySize, smem0);
    cudaFuncSetAttribute(k_gemm<F>,   cudaFuncAttributeMaxDynamicSharedMemorySize, smem1);

    // CSR build
    k_deg<<<gEdge, TB>>>(ei + Ee);       // dst half only
    k_scan<<<1, 1024>>>();
    k_fill<<<gEdge, TB>>>(ei);

    for (int l = 0; l < 3; l++) {
        if (l == 0) k_gemm<IND><<<gGemm, TB, smem0>>>(x, P[0][0], P[0][1], P[0][2], 0);
        else        k_gemm<F>  <<<gGemm, TB, smem1>>>(x, P[l][0], P[l][1], P[l][2], 1);
        k_layer<<<gLayer, TB>>>(l == 0 ? alpha_out : nullptr,
                                P[l][3], P[l][4], P[l][5], P[l][6], P[l][7]);
    }
    k_head<<<NGr, TB>>>(batch, fcW, fcb, out);
}

// round 16
// speedup vs baseline: 1.8082x; 1.0034x over previous
#include <cuda_runtime.h>
#include <cuda_bf16.h>
#include <math.h>

// ---------------- problem constants ----------------
constexpr int Nn  = 50000;
constexpr int Ee  = 800000;
constexpr int ET  = Ee + Nn;          // 850000
constexpr int Hh  = 4;
constexpr int Cc  = 16;
constexpr int F   = Hh * Cc;          // 64
constexpr int IND = 128;
constexpr int NGr = 128;
constexpr float NEG   = 0.2f;
constexpr float EPSbn = 1e-5f;

// ---------------- scratch ----------------
__device__ __nv_bfloat16 g_hb[Nn * F];  // projected features, bf16 (gather side)
__device__ float g_x  [Nn * F];
__device__ float g_as [Nn * Hh];      // float4[Nn]
__device__ float g_ad [Nn * Hh];
__device__ int   g_deg [Nn];          // zero-init; re-zeroed by k_scan each call
__device__ int   g_row [Nn + 1];      // CSR row starts, row[Nn]=ET
__device__ int   g_cur [Nn];
__device__ int2  g_es  [ET];          // (edge id, src node) by CSR position

__device__ __forceinline__ float tf32r(float f) {
    float r;
    asm("cvt.rna.tf32.f32 %0, %1;" : "=f"(r) : "f"(f));
    return r;
}

// ---------------- CSR build ----------------
__global__ void k_deg(const int* __restrict__ dst) {
    int e = blockIdx.x * blockDim.x + threadIdx.x;
    if (e >= ET) return;
    int d = (e < Ee) ? dst[e] : (e - Ee);
    atomicAdd(&g_deg[d], 1);
}

__global__ void k_scan() {
    __shared__ int wsum[32];
    __shared__ int s_off;
    int tid = threadIdx.x, lane = tid & 31, wid = tid >> 5;
    if (tid == 0) s_off = 0;
    __syncthreads();
    for (int t0 = 0; t0 < Nn; t0 += 4096) {
        int i4 = t0 + tid * 4;
        int4 d = make_int4(0, 0, 0, 0);
        if (i4 < Nn) d = *(const int4*)(g_deg + i4);
        int s = d.x + d.y + d.z + d.w;
        int v = s;
#pragma unroll
        for (int off = 1; off < 32; off <<= 1) {
            int t = __shfl_up_sync(0xffffffffu, v, off);
            if (lane >= off) v += t;
        }
        if (lane == 31) wsum[wid] = v;
        __syncthreads();
        if (wid == 0) {
            int w = wsum[lane];
#pragma unroll
            for (int off = 1; off < 32; off <<= 1) {
                int t = __shfl_up_sync(0xffffffffu, w, off);
                if (lane >= off) w += t;
            }
            wsum[lane] = w;
        }
        __syncthreads();
        int excl = v - s + (wid ? wsum[wid - 1] : 0) + s_off;
        if (i4 < Nn) {
            int4 r = make_int4(excl, excl + d.x, excl + d.x + d.y,
                               excl + d.x + d.y + d.z);
            *(int4*)(g_row + i4) = r;
            *(int4*)(g_cur + i4) = r;
            *(int4*)(g_deg + i4) = make_int4(0, 0, 0, 0);
        }
        __syncthreads();
        if (tid == 0) s_off += wsum[31];
        __syncthreads();
    }
    if (tid == 0) g_row[Nn] = ET;
}

__global__ void k_fill(const int* __restrict__ ei) {
    int e = blockIdx.x * blockDim.x + threadIdx.x;
    if (e >= ET) return;
    int s, d;
    if (e < Ee) { s = ei[e]; d = ei[Ee + e]; }
    else        { s = e - Ee; d = e - Ee; }
    int pos = atomicAdd(&g_cur[d], 1);
    g_es[pos] = make_int2(e, s);
}

// ---------------- GEMM via mma.sync tf32 + fused attention dots ----------------
// 8 warps x 16 nodes = 128 nodes/block. C[m16,n8] tiles: 8 n-tiles cover F=64.
// Smem rows padded to K+4 floats (16B-aligned, conflict-free fragment LDS).
template <int K>
__global__ void k_gemm(const float* __restrict__ xparam,
                       const float* __restrict__ W,
                       const float* __restrict__ att_s,
                       const float* __restrict__ att_d, int use_gx) {
    constexpr int KQ = K / 4;
    constexpr int KP = K + 4;
    extern __shared__ float smf[];
    float* sX = smf;              // [128][KP]
    float* sW = smf + 128 * KP;   // [64][KP]
    const float* __restrict__ xin = use_gx ? (const float*)g_x : xparam;
    const int tid = threadIdx.x;
    const int base = blockIdx.x * 128;

    for (int i = tid; i < F * KQ; i += 256) {
        int r = i / KQ, c4 = i % KQ;
        float4 w = ((const float4*)W)[i];
        w.x = tf32r(w.x); w.y = tf32r(w.y); w.z = tf32r(w.z); w.w = tf32r(w.w);
        *(float4*)(sW + r * KP + c4 * 4) = w;
    }
    for (int i = tid; i < 128 * KQ; i += 256) {
        int r = i / KQ, c4 = i % KQ;
        int n = base + r;
        float4 v = make_float4(0.f, 0.f, 0.f, 0.f);
        if (n < Nn) v = ((const float4*)xin)[(size_t)n * KQ + c4];
        v.x = tf32r(v.x); v.y = tf32r(v.y); v.z = tf32r(v.z); v.w = tf32r(v.w);
        *(float4*)(sX + r * KP + c4 * 4) = v;
    }
    __syncthreads();

    const int warp = tid >> 5, lane = tid & 31;
    const int grp = lane >> 2, tig = lane & 3;
    const float* xa = sX + (warp * 16) * KP;

    float c[8][4];
#pragma unroll
    for (int nt = 0; nt < 8; nt++)
#pragma unroll
        for (int j = 0; j < 4; j++) c[nt][j] = 0.f;

    for (int kk = 0; kk < K; kk += 8) {
        unsigned a0 = __float_as_uint(xa[grp * KP + kk + tig]);
        unsigned a1 = __float_as_uint(xa[(grp + 8) * KP + kk + tig]);
        unsigned a2 = __float_as_uint(xa[grp * KP + kk + tig + 4]);
        unsigned a3 = __float_as_uint(xa[(grp + 8) * KP + kk + tig + 4]);
#pragma unroll
        for (int nt = 0; nt < 8; nt++) {
            unsigned b0 = __float_as_uint(sW[(nt * 8 + grp) * KP + kk + tig]);
            unsigned b1 = __float_as_uint(sW[(nt * 8 + grp) * KP + kk + tig + 4]);
            asm volatile(
                "mma.sync.aligned.m16n8k8.row.col.f32.tf32.tf32.f32 "
                "{%0,%1,%2,%3}, {%4,%5,%6,%7}, {%8,%9}, {%0,%1,%2,%3};\n"
                : "+f"(c[nt][0]), "+f"(c[nt][1]), "+f"(c[nt][2]), "+f"(c[nt][3])
                : "r"(a0), "r"(a1), "r"(a2), "r"(a3), "r"(b0), "r"(b1));
        }
    }

    // Epilogue: bf16 h store + per-head attention dots (fp32 acc).
    // Thread holds channels {nt*8 + 2*tig, +1} for nodes n1 (rows c0,c1) and
    // n2 = n1+8 (rows c2,c3). Head of n-tile nt is nt>>1.
    int n1 = base + warp * 16 + grp;
    int n2 = n1 + 8;
    float vs1[4] = {0, 0, 0, 0}, vd1[4] = {0, 0, 0, 0};
    float vs2[4] = {0, 0, 0, 0}, vd2[4] = {0, 0, 0, 0};
#pragma unroll
    for (int nt = 0; nt < 8; nt++) {
        int ch0 = nt * 8 + 2 * tig;
        float as0 = att_s[ch0], as1 = att_s[ch0 + 1];
        float ad0 = att_d[ch0], ad1 = att_d[ch0 + 1];
        int h = nt >> 1;
        vs1[h] += c[nt][0] * as0 + c[nt][1] * as1;
        vd1[h] += c[nt][0] * ad0 + c[nt][1] * ad1;
        vs2[h] += c[nt][2] * as0 + c[nt][3] * as1;
        vd2[h] += c[nt][2] * ad0 + c[nt][3] * ad1;
        if (n1 < Nn)
            *(__nv_bfloat162*)(g_hb + (size_t)n1 * F + ch0) =
                __floats2bfloat162_rn(c[nt][0], c[nt][1]);
        if (n2 < Nn)
            *(__nv_bfloat162*)(g_hb + (size_t)n2 * F + ch0) =
                __floats2bfloat162_rn(c[nt][2], c[nt][3]);
    }
#pragma unroll
    for (int h = 0; h < 4; h++) {
        vs1[h] += __shfl_xor_sync(0xffffffffu, vs1[h], 1);
        vs1[h] += __shfl_xor_sync(0xffffffffu, vs1[h], 2);
        vd1[h] += __shfl_xor_sync(0xffffffffu, vd1[h], 1);
        vd1[h] += __shfl_xor_sync(0xffffffffu, vd1[h], 2);
        vs2[h] += __shfl_xor_sync(0xffffffffu, vs2[h], 1);
        vs2[h] += __shfl_xor_sync(0xffffffffu, vs2[h], 2);
        vd2[h] += __shfl_xor_sync(0xffffffffu, vd2[h], 1);
        vd2[h] += __shfl_xor_sync(0xffffffffu, vd2[h], 2);
    }
    if (tig == 0) {
        float4* __restrict__ as4 = (float4*)g_as;
        float4* __restrict__ ad4 = (float4*)g_ad;
        if (n1 < Nn) {
            as4[n1] = make_float4(vs1[0], vs1[1], vs1[2], vs1[3]);
            ad4[n1] = make_float4(vd1[0], vd1[1], vd1[2], vd1[3]);
        }
        if (n2 < Nn) {
            as4[n2] = make_float4(vs2[0], vs2[1], vs2[2], vs2[3]);
            ad4[n2] = make_float4(vd2[0], vd2[1], vd2[2], vd2[3]);
        }
    }
}

// ---------------- fused edge pipeline: e-values staged in SMEM ----------------
constexpr int DCAP = 128;
__global__ void __launch_bounds__(256) k_layer(
        float4* __restrict__ alpha_out,
        const float* __restrict__ bias, const float* __restrict__ gamma,
        const float* __restrict__ beta, const float* __restrict__ mu,
        const float* __restrict__ var) {
    __shared__ float4 sm_e[8][DCAP];
    __shared__ int    sm_s[8][DCAP];
    int w    = threadIdx.x >> 5;
    int node = (blockIdx.x * blockDim.x + threadIdx.x) >> 5;
    int lane = threadIdx.x & 31;
    int ro = g_row[node], dg = g_row[node + 1] - ro;
    const float4* __restrict__ as4 = (const float4*)g_as;
    float4 ad = ((const float4*)g_ad)[node];

    float z0 = 0.f, z1 = 0.f, z2 = 0.f, z3 = 0.f;
    for (int i = lane; i < dg; i += 32) {
        int2 p = g_es[ro + i];
        float4 as = as4[p.y];
        float l0 = as.x + ad.x; l0 = l0 > 0.f ? l0 : NEG * l0;
        float l1 = as.y + ad.y; l1 = l1 > 0.f ? l1 : NEG * l1;
        float l2 = as.z + ad.z; l2 = l2 > 0.f ? l2 : NEG * l2;
        float l3 = as.w + ad.w; l3 = l3 > 0.f ? l3 : NEG * l3;
        float4 e4 = make_float4(__expf(l0), __expf(l1), __expf(l2), __expf(l3));
        if (i < DCAP) { sm_e[w][i] = e4; sm_s[w][i] = p.y; }
        z0 += e4.x; z1 += e4.y; z2 += e4.z; z3 += e4.w;
    }
#pragma unroll
    for (int off = 16; off; off >>= 1) {
        z0 += __shfl_xor_sync(0xffffffffu, z0, off);
        z1 += __shfl_xor_sync(0xffffffffu, z1, off);
        z2 += __shfl_xor_sync(0xffffffffu, z2, off);
        z3 += __shfl_xor_sync(0xffffffffu, z3, off);
    }
    float i0 = 1.f / z0, i1 = 1.f / z1, i2 = 1.f / z2, i3 = 1.f / z3;
    __syncwarp();

    if (alpha_out) {
        for (int i = lane; i < dg; i += 32) {
            int2 p = g_es[ro + i];
            float4 ev;
            if (i < DCAP) ev = sm_e[w][i];
            else {
                float4 as = as4[p.y];
                float l0 = as.x + ad.x; l0 = l0 > 0.f ? l0 : NEG * l0;
                float l1 = as.y + ad.y; l1 = l1 > 0.f ? l1 : NEG * l1;
                float l2 = as.z + ad.z; l2 = l2 > 0.f ? l2 : NEG * l2;
                float l3 = as.w + ad.w; l3 = l3 > 0.f ? l3 : NEG * l3;
                ev = make_float4(__expf(l0), __expf(l1), __expf(l2), __expf(l3));
            }
            alpha_out[p.x] = make_float4(ev.x * i0, ev.y * i1, ev.z * i2, ev.w * i3);
        }
    }

    float inv = (lane & 16) ? ((lane & 8) ? i3 : i2) : ((lane & 8) ? i1 : i0);
    float ax = 0.f, ay = 0.f;
    int c = lane * 2;
    int cap = dg < DCAP ? dg : DCAP;
#pragma unroll 8
    for (int i = 0; i < cap; i++) {
        int s = sm_s[w][i];
        float4 ev = sm_e[w][i];
        float al = (lane & 16) ? ((lane & 8) ? ev.w : ev.z)
                               : ((lane & 8) ? ev.y : ev.x);
        __nv_bfloat162 hb = *(const __nv_bfloat162*)(g_hb + (size_t)s * F + c);
        float2 hv = __bfloat1622float2(hb);
        ax = fmaf(al, hv.x, ax);
        ay = fmaf(al, hv.y, ay);
    }
    for (int i = cap; i < dg; i++) {
        int2 p = g_es[ro + i];
        float4 as = as4[p.y];
        float l0 = as.x + ad.x; l0 = l0 > 0.f ? l0 : NEG * l0;
        float l1 = as.y + ad.y; l1 = l1 > 0.f ? l1 : NEG * l1;
        float l2 = as.z + ad.z; l2 = l2 > 0.f ? l2 : NEG * l2;
        float l3 = as.w + ad.w; l3 = l3 > 0.f ? l3 : NEG * l3;
        float4 ev = make_float4(__expf(l0), __expf(l1), __expf(l2), __expf(l3));
        float al = (lane & 16) ? ((lane & 8) ? ev.w : ev.z)
                               : ((lane & 8) ? ev.y : ev.x);
        __nv_bfloat162 hb = *(const __nv_bfloat162*)(g_hb + (size_t)p.y * F + c);
        float2 hv = __bfloat1622float2(hb);
        ax = fmaf(al, hv.x, ax);
        ay = fmaf(al, hv.y, ay);
    }
    ax *= inv; ay *= inv;

    float2 bi = *(const float2*)(bias + c);
    float2 ga = *(const float2*)(gamma + c);
    float2 be = *(const float2*)(beta + c);
    float2 m_ = *(const float2*)(mu + c);
    float2 va = *(const float2*)(var + c);
    float vx = fmaxf(ax + bi.x, 0.f);
    vx = ga.x * (vx - m_.x) * rsqrtf(va.x + EPSbn) + be.x;
    float vy = fmaxf(ay + bi.y, 0.f);
    vy = ga.y * (vy - m_.y) * rsqrtf(va.y + EPSbn) + be.y;
    *(float2*)(g_x + (size_t)node * F + c) = make_float2(vx, vy);
}

// ---------------- head: pool + FC + sigmoid ----------------
__global__ void k_head(const int* __restrict__ batch,
                       const float* __restrict__ fcW, const float* __restrict__ fcb,
                       float* __restrict__ out) {
    __shared__ float sh[4][F];
    int g = blockIdx.x;
    int tid = threadIdx.x;
    int sub = tid >> 6, c = tid & 63;
    int lo = 0, hi = Nn;
    while (lo < hi) { int m = (lo + hi) >> 1; if (batch[m] < g) lo = m + 1; else hi = m; }
    int r0 = lo;
    lo = 0; hi = Nn;
    while (lo < hi) { int m = (lo + hi) >> 1; if (batch[m] < g + 1) lo = m + 1; else hi = m; }
    int r1 = lo;

    float acc = 0.f;
    for (int n = r0 + sub; n < r1; n += 4) acc += g_x[(size_t)n * F + c];
    sh[sub][c] = acc;
    __syncthreads();
    if (sub == 0) {
        float cnt = fmaxf((float)(r1 - r0), 1.f);
        sh[0][c] = (sh[0][c] + sh[1][c] + sh[2][c] + sh[3][c]) / cnt * fcW[c];
    }
    __syncthreads();
    if (tid == 0) {
        float z = fcb[0];
        for (int i = 0; i < F; i++) z += sh[0][i];
        out[g] = 1.f / (1.f + expf(-z));
    }
}

// ---------------- launch ----------------
extern "C" void kernel_launch(void* const* d_in, const int* in_sizes, int n_in,
                              void* d_out, int out_size) {
    const float* x     = (const float*)d_in[0];
    const int*   ei    = (const int*)  d_in[1];
    const int*   batch = (const int*)  d_in[2];
    const float* P[3][8];
    for (int l = 0; l < 3; l++)
        for (int j = 0; j < 8; j++)
            P[l][j] = (const float*)d_in[3 + l * 8 + j];
    const float* fcW = (const float*)d_in[27];
    const float* fcb = (const float*)d_in[28];

    float* out = (float*)d_out;
    float4* alpha_out = (out_size >= NGr + ET * Hh) ? (float4*)(out + NGr) : nullptr;

    const int TB = 256;
    const int gEdge  = (ET + TB - 1) / TB;
    const int gLayer = Nn / 8;                     // warp per node
    const int gGemm  = (Nn + 127) / 128;           // 391

    const int smem0 = (128 + F) * (IND + 4) * (int)sizeof(float);  // ~101 KB
    const int smem1 = (128 + F) * (F + 4) * (int)sizeof(float);    // ~52 KB
    cudaFuncSetAttribute(k_gemm<IND>, cudaFuncAttributeMaxDynamicSharedMemorySize, smem0);
    cudaFuncSetAttribute(k_gemm<F>,   cudaFuncAttributeMaxDynamicSharedMemorySize, smem1);

    // CSR build
    k_deg<<<gEdge, TB>>>(ei + Ee);       // dst half only
    k_scan<<<1, 1024>>>();
    k_fill<<<gEdge, TB>>>(ei);

    for (int l = 0; l < 3; l++) {
        if (l == 0) k_gemm<IND><<<gGemm, TB, smem0>>>(x, P[0][0], P[0][1], P[0][2], 0);
        else        k_gemm<F>  <<<gGemm, TB, smem1>>>(x, P[l][0], P[l][1], P[l][2], 1);
        k_layer<<<gLayer, TB>>>(l == 0 ? alpha_out : nullptr,
                                P[l][3], P[l][4], P[l][5], P[l][6], P[l][7]);
    }
    k_head<<<NGr, TB>>>(batch, fcW, fcb, out);
}

// round 17
// speedup vs baseline: 1.8085x; 1.0002x over previous
#include <cuda_runtime.h>
#include <cuda_bf16.h>
#include <math.h>

// ---------------- problem constants ----------------
constexpr int Nn  = 50000;
constexpr int Ee  = 800000;
constexpr int ET  = Ee + Nn;          // 850000
constexpr int Hh  = 4;
constexpr int Cc  = 16;
constexpr int F   = Hh * Cc;          // 64
constexpr int IND = 128;
constexpr int NGr = 128;
constexpr float NEG   = 0.2f;
constexpr float EPSbn = 1e-5f;

// ---------------- scratch ----------------
__device__ __nv_bfloat16 g_hb[Nn * F];  // projected features, bf16 (gather side)
__device__ float g_x  [Nn * F];
__device__ float g_as [Nn * Hh];      // float4[Nn]
__device__ float g_ad [Nn * Hh];
__device__ int   g_deg [Nn];          // zero-init; re-zeroed by k_scan each call
__device__ int   g_row [Nn + 1];      // CSR row starts, row[Nn]=ET
__device__ int   g_cur [Nn];
__device__ int2  g_es  [ET];          // (edge id, src node) by CSR position

__device__ __forceinline__ float tf32r(float f) {
    float r;
    asm("cvt.rna.tf32.f32 %0, %1;" : "=f"(r) : "f"(f));
    return r;
}

// ---------------- CSR build ----------------
__global__ void k_deg(const int* __restrict__ dst) {
    int e = blockIdx.x * blockDim.x + threadIdx.x;
    if (e >= ET) return;
    int d = (e < Ee) ? dst[e] : (e - Ee);
    atomicAdd(&g_deg[d], 1);
}

__global__ void k_scan() {
    __shared__ int wsum[32];
    __shared__ int s_off;
    int tid = threadIdx.x, lane = tid & 31, wid = tid >> 5;
    if (tid == 0) s_off = 0;
    __syncthreads();
    for (int t0 = 0; t0 < Nn; t0 += 4096) {
        int i4 = t0 + tid * 4;
        int4 d = make_int4(0, 0, 0, 0);
        if (i4 < Nn) d = *(const int4*)(g_deg + i4);
        int s = d.x + d.y + d.z + d.w;
        int v = s;
#pragma unroll
        for (int off = 1; off < 32; off <<= 1) {
            int t = __shfl_up_sync(0xffffffffu, v, off);
            if (lane >= off) v += t;
        }
        if (lane == 31) wsum[wid] = v;
        __syncthreads();
        if (wid == 0) {
            int w = wsum[lane];
#pragma unroll
            for (int off = 1; off < 32; off <<= 1) {
                int t = __shfl_up_sync(0xffffffffu, w, off);
                if (lane >= off) w += t;
            }
            wsum[lane] = w;
        }
        __syncthreads();
        int excl = v - s + (wid ? wsum[wid - 1] : 0) + s_off;
        if (i4 < Nn) {
            int4 r = make_int4(excl, excl + d.x, excl + d.x + d.y,
                               excl + d.x + d.y + d.z);
            *(int4*)(g_row + i4) = r;
            *(int4*)(g_cur + i4) = r;
            *(int4*)(g_deg + i4) = make_int4(0, 0, 0, 0);
        }
        __syncthreads();
        if (tid == 0) s_off += wsum[31];
        __syncthreads();
    }
    if (tid == 0) g_row[Nn] = ET;
}

__global__ void k_fill(const int* __restrict__ ei) {
    int e = blockIdx.x * blockDim.x + threadIdx.x;
    if (e >= ET) return;
    int s, d;
    if (e < Ee) { s = ei[e]; d = ei[Ee + e]; }
    else        { s = e - Ee; d = e - Ee; }
    int pos = atomicAdd(&g_cur[d], 1);
    g_es[pos] = make_int2(e, s);
}

// ---------------- GEMM via mma.sync tf32 + fused attention dots ----------------
// 8 warps x 16 nodes = 128 nodes/block. A fragments loaded DIRECTLY from
// global (row stays L1-resident across k-steps); only W staged in smem
// (34KB K=128 / 17KB K=64) -> 4 CTAs/SM instead of 2.
template <int K>
__global__ void k_gemm(const float* __restrict__ xparam,
                       const float* __restrict__ W,
                       const float* __restrict__ att_s,
                       const float* __restrict__ att_d, int use_gx) {
    constexpr int KQ = K / 4;
    constexpr int KP = K + 4;
    extern __shared__ float smf[];
    float* sW = smf;              // [64][KP]
    const float* __restrict__ xin = use_gx ? (const float*)g_x : xparam;
    const int tid = threadIdx.x;
    const int base = blockIdx.x * 128;

    for (int i = tid; i < F * KQ; i += 256) {
        int r = i / KQ, c4 = i % KQ;
        float4 w = ((const float4*)W)[i];
        w.x = tf32r(w.x); w.y = tf32r(w.y); w.z = tf32r(w.z); w.w = tf32r(w.w);
        *(float4*)(sW + r * KP + c4 * 4) = w;
    }
    __syncthreads();

    const int warp = tid >> 5, lane = tid & 31;
    const int grp = lane >> 2, tig = lane & 3;

    const int n1 = base + warp * 16 + grp;
    const int n2 = n1 + 8;
    const bool v1 = n1 < Nn, v2 = n2 < Nn;
    const float* __restrict__ xr1 = xin + (size_t)(v1 ? n1 : 0) * K + tig;
    const float* __restrict__ xr2 = xin + (size_t)(v2 ? n2 : 0) * K + tig;

    float c[8][4];
#pragma unroll
    for (int nt = 0; nt < 8; nt++)
#pragma unroll
        for (int j = 0; j < 4; j++) c[nt][j] = 0.f;

#pragma unroll
    for (int kk = 0; kk < K; kk += 8) {
        unsigned a0 = __float_as_uint(tf32r(v1 ? __ldg(xr1 + kk) : 0.f));
        unsigned a1 = __float_as_uint(tf32r(v2 ? __ldg(xr2 + kk) : 0.f));
        unsigned a2 = __float_as_uint(tf32r(v1 ? __ldg(xr1 + kk + 4) : 0.f));
        unsigned a3 = __float_as_uint(tf32r(v2 ? __ldg(xr2 + kk + 4) : 0.f));
#pragma unroll
        for (int nt = 0; nt < 8; nt++) {
            unsigned b0 = __float_as_uint(sW[(nt * 8 + grp) * KP + kk + tig]);
            unsigned b1 = __float_as_uint(sW[(nt * 8 + grp) * KP + kk + tig + 4]);
            asm volatile(
                "mma.sync.aligned.m16n8k8.row.col.f32.tf32.tf32.f32 "
                "{%0,%1,%2,%3}, {%4,%5,%6,%7}, {%8,%9}, {%0,%1,%2,%3};\n"
                : "+f"(c[nt][0]), "+f"(c[nt][1]), "+f"(c[nt][2]), "+f"(c[nt][3])
                : "r"(a0), "r"(a1), "r"(a2), "r"(a3), "r"(b0), "r"(b1));
        }
    }

    // Epilogue: bf16 h store + per-head attention dots (fp32 acc).
    float vs1[4] = {0, 0, 0, 0}, vd1[4] = {0, 0, 0, 0};
    float vs2[4] = {0, 0, 0, 0}, vd2[4] = {0, 0, 0, 0};
#pragma unroll
    for (int nt = 0; nt < 8; nt++) {
        int ch0 = nt * 8 + 2 * tig;
        float as0 = att_s[ch0], as1 = att_s[ch0 + 1];
        float ad0 = att_d[ch0], ad1 = att_d[ch0 + 1];
        int h = nt >> 1;
        vs1[h] += c[nt][0] * as0 + c[nt][1] * as1;
        vd1[h] += c[nt][0] * ad0 + c[nt][1] * ad1;
        vs2[h] += c[nt][2] * as0 + c[nt][3] * as1;
        vd2[h] += c[nt][2] * ad0 + c[nt][3] * ad1;
        if (v1)
            *(__nv_bfloat162*)(g_hb + (size_t)n1 * F + ch0) =
                __floats2bfloat162_rn(c[nt][0], c[nt][1]);
        if (v2)
            *(__nv_bfloat162*)(g_hb + (size_t)n2 * F + ch0) =
                __floats2bfloat162_rn(c[nt][2], c[nt][3]);
    }
#pragma unroll
    for (int h = 0; h < 4; h++) {
        vs1[h] += __shfl_xor_sync(0xffffffffu, vs1[h], 1);
        vs1[h] += __shfl_xor_sync(0xffffffffu, vs1[h], 2);
        vd1[h] += __shfl_xor_sync(0xffffffffu, vd1[h], 1);
        vd1[h] += __shfl_xor_sync(0xffffffffu, vd1[h], 2);
        vs2[h] += __shfl_xor_sync(0xffffffffu, vs2[h], 1);
        vs2[h] += __shfl_xor_sync(0xffffffffu, vs2[h], 2);
        vd2[h] += __shfl_xor_sync(0xffffffffu, vd2[h], 1);
        vd2[h] += __shfl_xor_sync(0xffffffffu, vd2[h], 2);
    }
    if (tig == 0) {
        float4* __restrict__ as4 = (float4*)g_as;
        float4* __restrict__ ad4 = (float4*)g_ad;
        if (v1) {
            as4[n1] = make_float4(vs1[0], vs1[1], vs1[2], vs1[3]);
            ad4[n1] = make_float4(vd1[0], vd1[1], vd1[2], vd1[3]);
        }
        if (v2) {
            as4[n2] = make_float4(vs2[0], vs2[1], vs2[2], vs2[3]);
            ad4[n2] = make_float4(vd2[0], vd2[1], vd2[2], vd2[3]);
        }
    }
}

// ---------------- fused edge pipeline: e-values staged in SMEM ----------------
constexpr int DCAP = 128;
__global__ void __launch_bounds__(256) k_layer(
        float4* __restrict__ alpha_out,
        const float* __restrict__ bias, const float* __restrict__ gamma,
        const float* __restrict__ beta, const float* __restrict__ mu,
        const float* __restrict__ var) {
    __shared__ float4 sm_e[8][DCAP];
    __shared__ int    sm_s[8][DCAP];
    int w    = threadIdx.x >> 5;
    int node = (blockIdx.x * blockDim.x + threadIdx.x) >> 5;
    int lane = threadIdx.x & 31;
    int ro = g_row[node], dg = g_row[node + 1] - ro;
    const float4* __restrict__ as4 = (const float4*)g_as;
    float4 ad = ((const float4*)g_ad)[node];

    float z0 = 0.f, z1 = 0.f, z2 = 0.f, z3 = 0.f;
    for (int i = lane; i < dg; i += 32) {
        int2 p = g_es[ro + i];
        float4 as = as4[p.y];
        float l0 = as.x + ad.x; l0 = l0 > 0.f ? l0 : NEG * l0;
        float l1 = as.y + ad.y; l1 = l1 > 0.f ? l1 : NEG * l1;
        float l2 = as.z + ad.z; l2 = l2 > 0.f ? l2 : NEG * l2;
        float l3 = as.w + ad.w; l3 = l3 > 0.f ? l3 : NEG * l3;
        float4 e4 = make_float4(__expf(l0), __expf(l1), __expf(l2), __expf(l3));
        if (i < DCAP) { sm_e[w][i] = e4; sm_s[w][i] = p.y; }
        z0 += e4.x; z1 += e4.y; z2 += e4.z; z3 += e4.w;
    }
#pragma unroll
    for (int off = 16; off; off >>= 1) {
        z0 += __shfl_xor_sync(0xffffffffu, z0, off);
        z1 += __shfl_xor_sync(0xffffffffu, z1, off);
        z2 += __shfl_xor_sync(0xffffffffu, z2, off);
        z3 += __shfl_xor_sync(0xffffffffu, z3, off);
    }
    float i0 = 1.f / z0, i1 = 1.f / z1, i2 = 1.f / z2, i3 = 1.f / z3;
    __syncwarp();

    if (alpha_out) {
        for (int i = lane; i < dg; i += 32) {
            int2 p = g_es[ro + i];
            float4 ev;
            if (i < DCAP) ev = sm_e[w][i];
            else {
                float4 as = as4[p.y];
                float l0 = as.x + ad.x; l0 = l0 > 0.f ? l0 : NEG * l0;
                float l1 = as.y + ad.y; l1 = l1 > 0.f ? l1 : NEG * l1;
                float l2 = as.z + ad.z; l2 = l2 > 0.f ? l2 : NEG * l2;
                float l3 = as.w + ad.w; l3 = l3 > 0.f ? l3 : NEG * l3;
                ev = make_float4(__expf(l0), __expf(l1), __expf(l2), __expf(l3));
            }
            alpha_out[p.x] = make_float4(ev.x * i0, ev.y * i1, ev.z * i2, ev.w * i3);
        }
    }

    float inv = (lane & 16) ? ((lane & 8) ? i3 : i2) : ((lane & 8) ? i1 : i0);
    float ax = 0.f, ay = 0.f;
    int c = lane * 2;
    int cap = dg < DCAP ? dg : DCAP;
#pragma unroll 8
    for (int i = 0; i < cap; i++) {
        int s = sm_s[w][i];
        float4 ev = sm_e[w][i];
        float al = (lane & 16) ? ((lane & 8) ? ev.w : ev.z)
                               : ((lane & 8) ? ev.y : ev.x);
        __nv_bfloat162 hb = *(const __nv_bfloat162*)(g_hb + (size_t)s * F + c);
        float2 hv = __bfloat1622float2(hb);
        ax = fmaf(al, hv.x, ax);
        ay = fmaf(al, hv.y, ay);
    }
    for (int i = cap; i < dg; i++) {
        int2 p = g_es[ro + i];
        float4 as = as4[p.y];
        float l0 = as.x + ad.x; l0 = l0 > 0.f ? l0 : NEG * l0;
        float l1 = as.y + ad.y; l1 = l1 > 0.f ? l1 : NEG * l1;
        float l2 = as.z + ad.z; l2 = l2 > 0.f ? l2 : NEG * l2;
        float l3 = as.w + ad.w; l3 = l3 > 0.f ? l3 : NEG * l3;
        float4 ev = make_float4(__expf(l0), __expf(l1), __expf(l2), __expf(l3));
        float al = (lane & 16) ? ((lane & 8) ? ev.w : ev.z)
                               : ((lane & 8) ? ev.y : ev.x);
        __nv_bfloat162 hb = *(const __nv_bfloat162*)(g_hb + (size_t)p.y * F + c);
        float2 hv = __bfloat1622float2(hb);
        ax = fmaf(al, hv.x, ax);
        ay = fmaf(al, hv.y, ay);
    }
    ax *= inv; ay *= inv;

    float2 bi = *(const float2*)(bias + c);
    float2 ga = *(const float2*)(gamma + c);
    float2 be = *(const float2*)(beta + c);
    float2 m_ = *(const float2*)(mu + c);
    float2 va = *(const float2*)(var + c);
    float vx = fmaxf(ax + bi.x, 0.f);
    vx = ga.x * (vx - m_.x) * rsqrtf(va.x + EPSbn) + be.x;
    float vy = fmaxf(ay + bi.y, 0.f);
    vy = ga.y * (vy - m_.y) * rsqrtf(va.y + EPSbn) + be.y;
    *(float2*)(g_x + (size_t)node * F + c) = make_float2(vx, vy);
}

// ---------------- head: pool + FC + sigmoid ----------------
__global__ void k_head(const int* __restrict__ batch,
                       const float* __restrict__ fcW, const float* __restrict__ fcb,
                       float* __restrict__ out) {
    __shared__ float sh[4][F];
    int g = blockIdx.x;
    int tid = threadIdx.x;
    int sub = tid >> 6, c = tid & 63;
    int lo = 0, hi = Nn;
    while (lo < hi) { int m = (lo + hi) >> 1; if (batch[m] < g) lo = m + 1; else hi = m; }
    int r0 = lo;
    lo = 0; hi = Nn;
    while (lo < hi) { int m = (lo + hi) >> 1; if (batch[m] < g + 1) lo = m + 1; else hi = m; }
    int r1 = lo;

    float acc = 0.f;
    for (int n = r0 + sub; n < r1; n += 4) acc += g_x[(size_t)n * F + c];
    sh[sub][c] = acc;
    __syncthreads();
    if (sub == 0) {
        float cnt = fmaxf((float)(r1 - r0), 1.f);
        sh[0][c] = (sh[0][c] + sh[1][c] + sh[2][c] + sh[3][c]) / cnt * fcW[c];
    }
    __syncthreads();
    if (tid == 0) {
        float z = fcb[0];
        for (int i = 0; i < F; i++) z += sh[0][i];
        out[g] = 1.f / (1.f + expf(-z));
    }
}

// ---------------- launch ----------------
extern "C" void kernel_launch(void* const* d_in, const int* in_sizes, int n_in,
                              void* d_out, int out_size) {
    const float* x     = (const float*)d_in[0];
    const int*   ei    = (const int*)  d_in[1];
    const int*   batch = (const int*)  d_in[2];
    const float* P[3][8];
    for (int l = 0; l < 3; l++)
        for (int j = 0; j < 8; j++)
            P[l][j] = (const float*)d_in[3 + l * 8 + j];
    const float* fcW = (const float*)d_in[27];
    const float* fcb = (const float*)d_in[28];

    float* out = (float*)d_out;
    float4* alpha_out = (out_size >= NGr + ET * Hh) ? (float4*)(out + NGr) : nullptr;

    const int TB = 256;
    const int gEdge  = (ET + TB - 1) / TB;
    const int gLayer = Nn / 8;                     // warp per node
    const int gGemm  = (Nn + 127) / 128;           // 391

    const int smem0 = F * (IND + 4) * (int)sizeof(float);  // ~33.8 KB
    const int smem1 = F * (F + 4) * (int)sizeof(float);    // ~17.4 KB
    cudaFuncSetAttribute(k_gemm<IND>, cudaFuncAttributeMaxDynamicSharedMemorySize, smem0);
    cudaFuncSetAttribute(k_gemm<F>,   cudaFuncAttributeMaxDynamicSharedMemorySize, smem1);

    // CSR build
    k_deg<<<gEdge, TB>>>(ei + Ee);       // dst half only
    k_scan<<<1, 1024>>>();
    k_fill<<<gEdge, TB>>>(ei);

    for (int l = 0; l < 3; l++) {
        if (l == 0) k_gemm<IND><<<gGemm, TB, smem0>>>(x, P[0][0], P[0][1], P[0][2], 0);
        else        k_gemm<F>  <<<gGemm, TB, smem1>>>(x, P[l][0], P[l][1], P[l][2], 1);
        k_layer<<<gLayer, TB>>>(l == 0 ? alpha_out : nullptr,
                                P[l][3], P[l][4], P[l][5], P[l][6], P[l][7]);
    }
    k_head<<<NGr, TB>>>(batch, fcW, fcb, out);
}